// round 4
// baseline (speedup 1.0000x reference)
#include <cuda_runtime.h>
#include <cuda_bf16.h>
#include <math.h>
#include <stdint.h>

// ===========================================================================
// Problem constants (fixed shapes)
// ===========================================================================
#define NN     50000          // nodes
#define NNP    50048          // padded to 128
#define IND    3703           // input dim
#define INDP   3712           // padded to 64
#define HID    500
#define HSTR   512            // padded hidden
#define EMAX   1000000

// ===========================================================================
// Device scratch (static globals; no dynamic allocation)
// ===========================================================================
__device__ __nv_bfloat16 g_xhi[(size_t)NNP * INDP];
__device__ __nv_bfloat16 g_xlo[(size_t)NNP * INDP];
__device__ __nv_bfloat16 g_w1hi[HSTR * INDP];
__device__ __nv_bfloat16 g_w1lo[HSTR * INDP];
__device__ __nv_bfloat16 g_w2hi[HSTR * HSTR];
__device__ __nv_bfloat16 g_w2lo[HSTR * HSTR];
__device__ __nv_bfloat16 g_hhi[(size_t)NNP * HSTR];
__device__ __nv_bfloat16 g_hlo[(size_t)NNP * HSTR];
__device__ float g_a[(size_t)NNP * HSTR];    // GEMM output
__device__ float g_b[(size_t)NNP * HSTR];    // gather output (fp32)
__device__ float g_s1[(size_t)NNP * 8];      // layer-3 GEMM out

__device__ int   g_cnt[NNP];
__device__ int   g_part[NNP];
__device__ int   g_aux[256];
__device__ int   g_ptr[NN + 1];
__device__ int   g_wp[NNP];
__device__ int   g_csrc[EMAX];
__device__ float g_cw[EMAX];

// ===========================================================================
// Helpers
// ===========================================================================
__device__ __forceinline__ uint32_t smem_to_u32(const void* p) {
    uint32_t a;
    asm("{ .reg .u64 t; cvta.to.shared.u64 t, %1; cvt.u32.u64 %0, t; }"
        : "=r"(a) : "l"(p));
    return a;
}
__device__ __forceinline__ void ldsm4(uint32_t& r0, uint32_t& r1,
                                      uint32_t& r2, uint32_t& r3, uint32_t addr) {
    asm volatile("ldmatrix.sync.aligned.m8n8.x4.shared.b16 {%0,%1,%2,%3}, [%4];"
        : "=r"(r0), "=r"(r1), "=r"(r2), "=r"(r3) : "r"(addr));
}
__device__ __forceinline__ void mma16816(float* c, const uint32_t* a,
                                         uint32_t b0, uint32_t b1) {
    asm volatile("mma.sync.aligned.m16n8k16.row.col.f32.bf16.bf16.f32 "
        "{%0,%1,%2,%3}, {%4,%5,%6,%7}, {%8,%9}, {%0,%1,%2,%3};"
        : "+f"(c[0]), "+f"(c[1]), "+f"(c[2]), "+f"(c[3])
        : "r"(a[0]), "r"(a[1]), "r"(a[2]), "r"(a[3]), "r"(b0), "r"(b1));
}
__device__ __forceinline__ void cp16(uint32_t soff, const void* g) {
    asm volatile("cp.async.cg.shared.global [%0], [%1], 16;" :: "r"(soff), "l"(g));
}

__device__ __forceinline__ void split2(float v, __nv_bfloat16& h, __nv_bfloat16& l) {
    h = __float2bfloat16_rn(v);
    l = __float2bfloat16_rn(v - __bfloat162float(h));
}
__device__ __forceinline__ uint32_t pk(__nv_bfloat16 a, __nv_bfloat16 b) {
    return (uint32_t)__bfloat16_as_ushort(a) | ((uint32_t)__bfloat16_as_ushort(b) << 16);
}

// ===========================================================================
// X -> bf16 hi/lo split
// ===========================================================================
#define XCHUNKS (INDP / 8)   // 464
__global__ __launch_bounds__(256)
void split_x_kernel(const float* __restrict__ x,
                    __nv_bfloat16* __restrict__ xh, __nv_bfloat16* __restrict__ xl)
{
    int idx = blockIdx.x * 256 + threadIdx.x;
    int total = NN * XCHUNKS;
    if (idx >= total) return;
    int row = idx / XCHUNKS;
    int cb  = (idx - row * XCHUNKS) * 8;
    const float* px = x + (size_t)row * IND;
    __nv_bfloat16 hh[8], ll[8];
#pragma unroll
    for (int j = 0; j < 8; j++) {
        int c = cb + j;
        float v = (c < IND) ? px[c] : 0.f;
        split2(v, hh[j], ll[j]);
    }
    size_t off = (size_t)row * INDP + cb;
    uint4 uh, ul;
    uh.x = pk(hh[0], hh[1]); uh.y = pk(hh[2], hh[3]);
    uh.z = pk(hh[4], hh[5]); uh.w = pk(hh[6], hh[7]);
    ul.x = pk(ll[0], ll[1]); ul.y = pk(ll[2], ll[3]);
    ul.z = pk(ll[4], ll[5]); ul.w = pk(ll[6], ll[7]);
    *(uint4*)(xh + off) = uh;
    *(uint4*)(xl + off) = ul;
}

// ===========================================================================
// Weight prep: w [K x N] fp32 -> transposed padded hi/lo [NP][KP] bf16
// ===========================================================================
__global__ void prep_w_kernel(const float* __restrict__ w,
                              __nv_bfloat16* __restrict__ dh,
                              __nv_bfloat16* __restrict__ dl,
                              int K, int N, int KP, int NP)
{
    int idx = blockIdx.x * 256 + threadIdx.x;
    if (idx >= NP * KP) return;
    int n = idx / KP, k = idx - n * KP;
    float v = (k < K && n < N) ? __ldg(&w[(size_t)k * N + n]) : 0.f;
    __nv_bfloat16 h, l;
    split2(v, h, l);
    dh[idx] = h; dl[idx] = l;
}

// ===========================================================================
// CSR build
// ===========================================================================
__global__ void cnt_zero_kernel(int* __restrict__ cnt) {
    int i = blockIdx.x * 256 + threadIdx.x;
    if (i < NNP) cnt[i] = 0;
}
__global__ void hist_kernel(const int* __restrict__ ed, int* __restrict__ cnt, int E) {
    int e = blockIdx.x * 256 + threadIdx.x;
    if (e < E) atomicAdd(&cnt[ed[e]], 1);
}
__global__ void scan1_kernel(const int* __restrict__ cnt, int* __restrict__ part,
                             int* __restrict__ aux, int n)
{
    __shared__ int s[256];
    int tid = threadIdx.x;
    int g = blockIdx.x * 256 + tid;
    int v = (g < n) ? cnt[g] : 0;
    s[tid] = v;
    __syncthreads();
#pragma unroll
    for (int o = 1; o < 256; o <<= 1) {
        int t = (tid >= o) ? s[tid - o] : 0;
        __syncthreads();
        s[tid] += t;
        __syncthreads();
    }
    if (g < n) part[g] = s[tid] - v;
    if (tid == 255) aux[blockIdx.x] = s[tid];
}
__global__ void scan2_kernel(int* __restrict__ aux, int nb)
{
    __shared__ int s[256];
    int tid = threadIdx.x;
    int v = (tid < nb) ? aux[tid] : 0;
    s[tid] = v;
    __syncthreads();
#pragma unroll
    for (int o = 1; o < 256; o <<= 1) {
        int t = (tid >= o) ? s[tid - o] : 0;
        __syncthreads();
        s[tid] += t;
        __syncthreads();
    }
    if (tid < nb) aux[tid] = s[tid] - v;   // exclusive
}
__global__ void scan3_kernel(const int* __restrict__ part, const int* __restrict__ aux,
                             int* __restrict__ ptr, int* __restrict__ wp, int n, int E)
{
    int g = blockIdx.x * 256 + threadIdx.x;
    if (g < n) {
        int v = part[g] + aux[g >> 8];
        ptr[g] = v;
        wp[g] = v;
    }
    if (g == 0) ptr[n] = E;
}
__global__ void fill_kernel(const int* __restrict__ es, const int* __restrict__ ed,
                            const float* __restrict__ ew, int* __restrict__ wp,
                            int* __restrict__ csrc, float* __restrict__ cw, int E)
{
    int e = blockIdx.x * 256 + threadIdx.x;
    if (e >= E) return;
    int d = ed[e];
    int p = atomicAdd(&wp[d], 1);
    csrc[p] = es[e];
    cw[p] = ew[e];
}

// ===========================================================================
// HMMA GEMM: C[M x 512] = A[M x K] @ B^T[512 x K], bf16 3-term split
// CTA 128x128, BK=32, 256 threads, warp tile 64x32 (2m x 4n warps)
// 3-stage cp.async pipeline, ONE __syncthreads per K-iteration:
//   iter kc: wait_group(1) -> barrier -> compute(stage kc%3)
//            -> issue loads for stage kc+2 (writes (kc+2)%3 == (kc-1)%3,
//               safe: barrier guaranteed all warps finished compute(kc-1)).
// Swizzle: 16B chunk c of row r at c ^ ((r>>1)&3) -> conflict-free for both
// cp.async stores and ldmatrix.x4 reads.
// ===========================================================================
#define STG    32768
#define NSTAGE 3

__global__ __launch_bounds__(256)
void gemm_hmma_kernel(const __nv_bfloat16* __restrict__ Ah,
                      const __nv_bfloat16* __restrict__ Al, int lda,
                      const __nv_bfloat16* __restrict__ Bh,
                      const __nv_bfloat16* __restrict__ Bl, int ldb,
                      float* __restrict__ C, int ldc, int nkc)
{
    extern __shared__ char smem[];
    const uint32_t sb = smem_to_u32(smem);
    const int tid  = threadIdx.x;
    const int lane = tid & 31;
    const int wid  = tid >> 5;
    const int m0 = blockIdx.y * 128;
    const int n0 = blockIdx.x * 128;
    const int wm = (wid >> 2) * 64;
    const int wn = (wid & 3) * 32;

    float acc[4][4][4];
#pragma unroll
    for (int i = 0; i < 4; i++)
#pragma unroll
        for (int j = 0; j < 4; j++)
#pragma unroll
            for (int q = 0; q < 4; q++) acc[i][j][q] = 0.f;

    auto load_stage = [&](int kc, int s) {
        int kk = kc * 32;
#pragma unroll
        for (int j = 0; j < 8; j++) {
            int id = tid + j * 256;
            int tile = id >> 9;               // 0..3
            int r = (id >> 2) & 127;
            int c = id & 3;
            uint32_t soff = sb + s * STG + tile * 8192 + r * 64
                          + ((c ^ ((r >> 1) & 3)) << 4);
            const __nv_bfloat16* g;
            if (tile == 0)      g = Ah + (size_t)(m0 + r) * lda + kk + c * 8;
            else if (tile == 1) g = Al + (size_t)(m0 + r) * lda + kk + c * 8;
            else if (tile == 2) g = Bh + (size_t)(n0 + r) * ldb + kk + c * 8;
            else                g = Bl + (size_t)(n0 + r) * ldb + kk + c * 8;
            cp16(soff, g);
        }
        asm volatile("cp.async.commit_group;");
    };

    // prologue: stages 0..NSTAGE-2
    load_stage(0, 0);
    load_stage(1, 1);

    for (int kc = 0; kc < nkc; kc++) {
        int s = kc % NSTAGE;
        asm volatile("cp.async.wait_group 1;");
        __syncthreads();

        uint32_t tAh = sb + s * STG;
        uint32_t tAl = tAh + 8192;
        uint32_t tBh = tAh + 16384;
        uint32_t tBl = tAh + 24576;

#pragma unroll
        for (int kh = 0; kh < 2; kh++) {
            uint32_t ah[4][4], al[4][4], bh[2][4], bl[2][4];
            const int rlo = lane & 15;
            const int q   = 2 * kh + (lane >> 4);
#pragma unroll
            for (int i = 0; i < 4; i++) {
                int r = wm + i * 16 + rlo;
                uint32_t off = r * 64 + ((q ^ ((r >> 1) & 3)) << 4);
                ldsm4(ah[i][0], ah[i][1], ah[i][2], ah[i][3], tAh + off);
                ldsm4(al[i][0], al[i][1], al[i][2], al[i][3], tAl + off);
            }
#pragma unroll
            for (int j = 0; j < 2; j++) {
                int r = wn + j * 16 + rlo;
                uint32_t off = r * 64 + ((q ^ ((r >> 1) & 3)) << 4);
                ldsm4(bh[j][0], bh[j][1], bh[j][2], bh[j][3], tBh + off);
                ldsm4(bl[j][0], bl[j][1], bl[j][2], bl[j][3], tBl + off);
            }
#pragma unroll
            for (int i = 0; i < 4; i++) {
#pragma unroll
                for (int jj = 0; jj < 4; jj++) {
                    uint32_t bh0 = bh[jj >> 1][jj & 1];
                    uint32_t bh1 = bh[jj >> 1][(jj & 1) + 2];
                    uint32_t bl0 = bl[jj >> 1][jj & 1];
                    uint32_t bl1 = bl[jj >> 1][(jj & 1) + 2];
                    mma16816(acc[i][jj], ah[i], bh0, bh1);
                    mma16816(acc[i][jj], ah[i], bl0, bl1);
                    mma16816(acc[i][jj], al[i], bh0, bh1);
                }
            }
        }

        if (kc + NSTAGE - 1 < nkc)
            load_stage(kc + NSTAGE - 1, (kc + NSTAGE - 1) % NSTAGE);
    }

    // epilogue
#pragma unroll
    for (int i = 0; i < 4; i++) {
        int row = m0 + wm + i * 16 + (lane >> 2);
#pragma unroll
        for (int jj = 0; jj < 4; jj++) {
            int col = n0 + wn + jj * 8 + 2 * (lane & 3);
            float2 v0 = make_float2(acc[i][jj][0], acc[i][jj][1]);
            float2 v1 = make_float2(acc[i][jj][2], acc[i][jj][3]);
            *(float2*)(C + (size_t)row * ldc + col) = v0;
            *(float2*)(C + (size_t)(row + 8) * ldc + col) = v1;
        }
    }
}

// ===========================================================================
// CSR gather: out[node] = relu( sum_e w*src[srcnode] + bias )
// block = 128 threads per node; each thread owns 4 columns.
// ===========================================================================
__global__ __launch_bounds__(128)
void gather_kernel(const float* __restrict__ src, const int* __restrict__ ptr,
                   const int* __restrict__ cs, const float* __restrict__ cw,
                   const float* __restrict__ bias,
                   float* __restrict__ outf,
                   __nv_bfloat16* __restrict__ oh, __nv_bfloat16* __restrict__ ol)
{
    int node = blockIdx.x;
    int tid = threadIdx.x;
    int beg = ptr[node], end = ptr[node + 1];
    float a0 = 0.f, a1 = 0.f, a2 = 0.f, a3 = 0.f;
    const int c0 = tid, c1 = tid + 128, c2 = tid + 256, c3 = tid + 384;
    for (int i = beg; i < end; i++) {
        int s = cs[i];
        float w = cw[i];
        const float* ps = src + (size_t)s * HSTR;
        a0 = fmaf(w, ps[c0], a0);
        a1 = fmaf(w, ps[c1], a1);
        a2 = fmaf(w, ps[c2], a2);
        a3 = fmaf(w, ps[c3], a3);
    }
    float v0 = fmaxf(a0 + bias[c0], 0.f);
    float v1 = fmaxf(a1 + bias[c1], 0.f);
    float v2 = fmaxf(a2 + bias[c2], 0.f);
    float v3 = fmaxf(a3 + ((c3 < HID) ? bias[c3] : 0.f), 0.f);
    size_t base = (size_t)node * HSTR;
    if (outf) {
        outf[base + c0] = v0; outf[base + c1] = v1;
        outf[base + c2] = v2; outf[base + c3] = v3;
    }
    if (oh) {
        __nv_bfloat16 h, l;
        split2(v0, h, l); oh[base + c0] = h; ol[base + c0] = l;
        split2(v1, h, l); oh[base + c1] = h; ol[base + c1] = l;
        split2(v2, h, l); oh[base + c2] = h; ol[base + c2] = l;
        split2(v3, h, l); oh[base + c3] = h; ol[base + c3] = l;
    }
}

// ===========================================================================
// GEMM3: warp-per-row, s1[row,0..5] = H[row,:] @ W3   (K=500, N=6)
// ===========================================================================
__global__ void gemm3_kernel(const float* __restrict__ H,
                             const float* __restrict__ W,
                             float* __restrict__ out, int M)
{
    int row  = blockIdx.x * (blockDim.x >> 5) + (threadIdx.x >> 5);
    int lane = threadIdx.x & 31;
    if (row >= M) return;
    const float* ph = H + (size_t)row * HSTR;
    float acc[6] = {0.f, 0.f, 0.f, 0.f, 0.f, 0.f};
    for (int k = lane; k < HID; k += 32) {
        float a = ph[k];
        const float* pw = W + (size_t)k * 6;
#pragma unroll
        for (int j = 0; j < 6; j++) acc[j] = fmaf(a, pw[j], acc[j]);
    }
#pragma unroll
    for (int j = 0; j < 6; j++)
#pragma unroll
        for (int off = 16; off > 0; off >>= 1)
            acc[j] += __shfl_xor_sync(0xffffffffu, acc[j], off);
    if (lane == 0) {
        float* po = out + (size_t)row * 8;
#pragma unroll
        for (int j = 0; j < 6; j++) po[j] = acc[j];
    }
}

// ===========================================================================
// Final fused: aggregate (CSR) + b3 + log_softmax, warp per node
// ===========================================================================
__global__ void final_kernel(const float* __restrict__ s1, const int* __restrict__ ptr,
                             const int* __restrict__ cs, const float* __restrict__ cw,
                             const float* __restrict__ b3, float* __restrict__ out, int M)
{
    int node = (blockIdx.x * blockDim.x + threadIdx.x) >> 5;
    int lane = threadIdx.x & 31;
    if (node >= M) return;
    int beg = ptr[node], end = ptr[node + 1];
    float a[6] = {0.f, 0.f, 0.f, 0.f, 0.f, 0.f};
    for (int i = beg + lane; i < end; i += 32) {
        int s = cs[i];
        float w = cw[i];
        const float* ps = s1 + (size_t)s * 8;
#pragma unroll
        for (int j = 0; j < 6; j++) a[j] = fmaf(w, ps[j], a[j]);
    }
#pragma unroll
    for (int j = 0; j < 6; j++)
#pragma unroll
        for (int off = 16; off > 0; off >>= 1)
            a[j] += __shfl_xor_sync(0xffffffffu, a[j], off);
    if (lane == 0) {
        float v[6];
#pragma unroll
        for (int j = 0; j < 6; j++) v[j] = a[j] + b3[j];
        float m = v[0];
#pragma unroll
        for (int j = 1; j < 6; j++) m = fmaxf(m, v[j]);
        float s = 0.f;
#pragma unroll
        for (int j = 0; j < 6; j++) s += __expf(v[j] - m);
        float l = logf(s) + m;
        float* po = out + (size_t)node * 6;
#pragma unroll
        for (int j = 0; j < 6; j++) po[j] = v[j] - l;
    }
}

// ===========================================================================
// Launch
// ===========================================================================
extern "C" void kernel_launch(void* const* d_in, const int* in_sizes, int n_in,
                              void* d_out, int out_size)
{
    const float* x   = (const float*)d_in[0];
    const float* w1  = (const float*)d_in[1];
    const float* b1  = (const float*)d_in[2];
    const float* w2  = (const float*)d_in[3];
    const float* b2  = (const float*)d_in[4];
    const float* w3  = (const float*)d_in[5];
    const float* b3  = (const float*)d_in[6];
    const float* ew  = (const float*)d_in[7];
    const int*   es  = (const int*)d_in[8];
    const int*   ed  = (const int*)d_in[9];
    float* out = (float*)d_out;

    const int E = in_sizes[7];

    __nv_bfloat16 *xhi, *xlo, *w1hi, *w1lo, *w2hi, *w2lo, *hhi, *hlo;
    float *pa, *pb, *ps1, *cwv;
    int *cnt, *part, *aux, *ptr, *wp, *csrc;
    cudaGetSymbolAddress((void**)&xhi,  g_xhi);
    cudaGetSymbolAddress((void**)&xlo,  g_xlo);
    cudaGetSymbolAddress((void**)&w1hi, g_w1hi);
    cudaGetSymbolAddress((void**)&w1lo, g_w1lo);
    cudaGetSymbolAddress((void**)&w2hi, g_w2hi);
    cudaGetSymbolAddress((void**)&w2lo, g_w2lo);
    cudaGetSymbolAddress((void**)&hhi,  g_hhi);
    cudaGetSymbolAddress((void**)&hlo,  g_hlo);
    cudaGetSymbolAddress((void**)&pa,   g_a);
    cudaGetSymbolAddress((void**)&pb,   g_b);
    cudaGetSymbolAddress((void**)&ps1,  g_s1);
    cudaGetSymbolAddress((void**)&cnt,  g_cnt);
    cudaGetSymbolAddress((void**)&part, g_part);
    cudaGetSymbolAddress((void**)&aux,  g_aux);
    cudaGetSymbolAddress((void**)&ptr,  g_ptr);
    cudaGetSymbolAddress((void**)&wp,   g_wp);
    cudaGetSymbolAddress((void**)&csrc, g_csrc);
    cudaGetSymbolAddress((void**)&cwv,  g_cw);

    cudaFuncSetAttribute(gemm_hmma_kernel,
                         cudaFuncAttributeMaxDynamicSharedMemorySize, NSTAGE * STG);

    dim3 ggrid(HSTR / 128, NNP / 128);   // (4, 391), N fastest for A L2 reuse

    // ---- input prep (ordered so gemm1 is the 4th launch -> gets profiled) ----
    {
        int total = NN * XCHUNKS;
        split_x_kernel<<<(total + 255) / 256, 256>>>(x, xhi, xlo);           // #1
    }
    prep_w_kernel<<<(HSTR * INDP + 255) / 256, 256>>>(w1, w1hi, w1lo,
                                                      IND, HID, INDP, HSTR); // #2
    prep_w_kernel<<<(HSTR * HSTR + 255) / 256, 256>>>(w2, w2hi, w2lo,
                                                      HID, HID, HSTR, HSTR); // #3

    // ---- Layer 1 GEMM ----                                                // #4
    gemm_hmma_kernel<<<ggrid, 256, NSTAGE * STG>>>(xhi, xlo, INDP, w1hi, w1lo, INDP,
                                                   pa, HSTR, INDP / 32);

    // ---- CSR build (only needed before gather) ----
    cnt_zero_kernel<<<(NNP + 255) / 256, 256>>>(cnt);                        // #5
    hist_kernel<<<(E + 255) / 256, 256>>>(ed, cnt, E);                       // #6
    {
        int nb = (NN + 255) / 256;   // 196
        scan1_kernel<<<nb, 256>>>(cnt, part, aux, NN);                       // #7
        scan2_kernel<<<1, 256>>>(aux, nb);                                   // #8
        scan3_kernel<<<nb, 256>>>(part, aux, ptr, wp, NN, E);                // #9
    }
    fill_kernel<<<(E + 255) / 256, 256>>>(es, ed, ew, wp, csrc, cwv, E);     // #10

    // ---- Layer 1 aggregate ----
    gather_kernel<<<NN, 128>>>(pa, ptr, csrc, cwv, b1, nullptr, hhi, hlo);   // #11

    // ---- Layer 2 ----
    gemm_hmma_kernel<<<ggrid, 256, NSTAGE * STG>>>(hhi, hlo, HSTR, w2hi, w2lo, HSTR,
                                                   pa, HSTR, HSTR / 32);     // #12
    gather_kernel<<<NN, 128>>>(pa, ptr, csrc, cwv, b2, pb, nullptr, nullptr);// #13

    // ---- Layer 3 ----
    gemm3_kernel<<<(NN + 7) / 8, 256>>>(pb, w3, ps1, NN);                    // #14
    final_kernel<<<(NN + 7) / 8, 256>>>(ps1, ptr, csrc, cwv, b3, out, NN);   // #15

    (void)n_in; (void)out_size;
}

// round 5
// speedup vs baseline: 1.4843x; 1.4843x over previous
#include <cuda_runtime.h>
#include <cuda_bf16.h>
#include <math.h>
#include <stdint.h>

// ===========================================================================
// Problem constants (fixed shapes)
// ===========================================================================
#define NN     50000          // nodes
#define NNP    50048          // padded to 128
#define IND    3703           // input dim
#define INDP   3712           // padded to 64
#define HID    500
#define HSTR   512            // padded hidden
#define EMAX   1000000

// ===========================================================================
// Device scratch (static globals; no dynamic allocation)
// ===========================================================================
__device__ __nv_bfloat16 g_xhi[(size_t)NNP * INDP];
__device__ __nv_bfloat16 g_xlo[(size_t)NNP * INDP];
__device__ __nv_bfloat16 g_w1hi[HSTR * INDP];
__device__ __nv_bfloat16 g_w1lo[HSTR * INDP];
__device__ __nv_bfloat16 g_w2hi[HSTR * HSTR];
__device__ __nv_bfloat16 g_w2lo[HSTR * HSTR];
__device__ __nv_bfloat16 g_hhi[(size_t)NNP * HSTR];
__device__ __nv_bfloat16 g_hlo[(size_t)NNP * HSTR];
__device__ float g_a[(size_t)NNP * HSTR];    // GEMM output
__device__ float g_s1[(size_t)NNP * 8];      // layer-3 per-node logits (pre-agg)

__device__ int   g_cnt[NNP];
__device__ int   g_part[NNP];
__device__ int   g_aux[256];
__device__ int   g_ptr[NN + 1];
__device__ int   g_wp[NNP];
__device__ int   g_csrc[EMAX];
__device__ float g_cw[EMAX];

// ===========================================================================
// Helpers
// ===========================================================================
__device__ __forceinline__ uint32_t smem_to_u32(const void* p) {
    uint32_t a;
    asm("{ .reg .u64 t; cvta.to.shared.u64 t, %1; cvt.u32.u64 %0, t; }"
        : "=r"(a) : "l"(p));
    return a;
}
__device__ __forceinline__ void ldsm4(uint32_t& r0, uint32_t& r1,
                                      uint32_t& r2, uint32_t& r3, uint32_t addr) {
    asm volatile("ldmatrix.sync.aligned.m8n8.x4.shared.b16 {%0,%1,%2,%3}, [%4];"
        : "=r"(r0), "=r"(r1), "=r"(r2), "=r"(r3) : "r"(addr));
}
__device__ __forceinline__ void mma16816(float* c, const uint32_t* a,
                                         uint32_t b0, uint32_t b1) {
    asm volatile("mma.sync.aligned.m16n8k16.row.col.f32.bf16.bf16.f32 "
        "{%0,%1,%2,%3}, {%4,%5,%6,%7}, {%8,%9}, {%0,%1,%2,%3};"
        : "+f"(c[0]), "+f"(c[1]), "+f"(c[2]), "+f"(c[3])
        : "r"(a[0]), "r"(a[1]), "r"(a[2]), "r"(a[3]), "r"(b0), "r"(b1));
}
__device__ __forceinline__ void cp16(uint32_t soff, const void* g) {
    asm volatile("cp.async.cg.shared.global [%0], [%1], 16;" :: "r"(soff), "l"(g));
}

__device__ __forceinline__ void split2(float v, __nv_bfloat16& h, __nv_bfloat16& l) {
    h = __float2bfloat16_rn(v);
    l = __float2bfloat16_rn(v - __bfloat162float(h));
}
__device__ __forceinline__ uint32_t pk(__nv_bfloat16 a, __nv_bfloat16 b) {
    return (uint32_t)__bfloat16_as_ushort(a) | ((uint32_t)__bfloat16_as_ushort(b) << 16);
}

// ===========================================================================
// X -> bf16 hi/lo split
// ===========================================================================
#define XCHUNKS (INDP / 8)   // 464
__global__ __launch_bounds__(256)
void split_x_kernel(const float* __restrict__ x,
                    __nv_bfloat16* __restrict__ xh, __nv_bfloat16* __restrict__ xl)
{
    int idx = blockIdx.x * 256 + threadIdx.x;
    int total = NN * XCHUNKS;
    if (idx >= total) return;
    int row = idx / XCHUNKS;
    int cb  = (idx - row * XCHUNKS) * 8;
    const float* px = x + (size_t)row * IND;
    __nv_bfloat16 hh[8], ll[8];
#pragma unroll
    for (int j = 0; j < 8; j++) {
        int c = cb + j;
        float v = (c < IND) ? px[c] : 0.f;
        split2(v, hh[j], ll[j]);
    }
    size_t off = (size_t)row * INDP + cb;
    uint4 uh, ul;
    uh.x = pk(hh[0], hh[1]); uh.y = pk(hh[2], hh[3]);
    uh.z = pk(hh[4], hh[5]); uh.w = pk(hh[6], hh[7]);
    ul.x = pk(ll[0], ll[1]); ul.y = pk(ll[2], ll[3]);
    ul.z = pk(ll[4], ll[5]); ul.w = pk(ll[6], ll[7]);
    *(uint4*)(xh + off) = uh;
    *(uint4*)(xl + off) = ul;
}

// ===========================================================================
// Weight prep: w [K x N] fp32 -> transposed padded hi/lo [NP][KP] bf16
// ===========================================================================
__global__ void prep_w_kernel(const float* __restrict__ w,
                              __nv_bfloat16* __restrict__ dh,
                              __nv_bfloat16* __restrict__ dl,
                              int K, int N, int KP, int NP)
{
    int idx = blockIdx.x * 256 + threadIdx.x;
    if (idx >= NP * KP) return;
    int n = idx / KP, k = idx - n * KP;
    float v = (k < K && n < N) ? __ldg(&w[(size_t)k * N + n]) : 0.f;
    __nv_bfloat16 h, l;
    split2(v, h, l);
    dh[idx] = h; dl[idx] = l;
}

// ===========================================================================
// CSR build
// ===========================================================================
__global__ void cnt_zero_kernel(int* __restrict__ cnt) {
    int i = blockIdx.x * 256 + threadIdx.x;
    if (i < NNP) cnt[i] = 0;
}
__global__ void hist_kernel(const int* __restrict__ ed, int* __restrict__ cnt, int E) {
    int e = blockIdx.x * 256 + threadIdx.x;
    if (e < E) atomicAdd(&cnt[ed[e]], 1);
}
__global__ void scan1_kernel(const int* __restrict__ cnt, int* __restrict__ part,
                             int* __restrict__ aux, int n)
{
    __shared__ int s[256];
    int tid = threadIdx.x;
    int g = blockIdx.x * 256 + tid;
    int v = (g < n) ? cnt[g] : 0;
    s[tid] = v;
    __syncthreads();
#pragma unroll
    for (int o = 1; o < 256; o <<= 1) {
        int t = (tid >= o) ? s[tid - o] : 0;
        __syncthreads();
        s[tid] += t;
        __syncthreads();
    }
    if (g < n) part[g] = s[tid] - v;
    if (tid == 255) aux[blockIdx.x] = s[tid];
}
__global__ void scan2_kernel(int* __restrict__ aux, int nb)
{
    __shared__ int s[256];
    int tid = threadIdx.x;
    int v = (tid < nb) ? aux[tid] : 0;
    s[tid] = v;
    __syncthreads();
#pragma unroll
    for (int o = 1; o < 256; o <<= 1) {
        int t = (tid >= o) ? s[tid - o] : 0;
        __syncthreads();
        s[tid] += t;
        __syncthreads();
    }
    if (tid < nb) aux[tid] = s[tid] - v;   // exclusive
}
__global__ void scan3_kernel(const int* __restrict__ part, const int* __restrict__ aux,
                             int* __restrict__ ptr, int* __restrict__ wp, int n, int E)
{
    int g = blockIdx.x * 256 + threadIdx.x;
    if (g < n) {
        int v = part[g] + aux[g >> 8];
        ptr[g] = v;
        wp[g] = v;
    }
    if (g == 0) ptr[n] = E;
}
__global__ void fill_kernel(const int* __restrict__ es, const int* __restrict__ ed,
                            const float* __restrict__ ew, int* __restrict__ wp,
                            int* __restrict__ csrc, float* __restrict__ cw, int E)
{
    int e = blockIdx.x * 256 + threadIdx.x;
    if (e >= E) return;
    int d = ed[e];
    int p = atomicAdd(&wp[d], 1);
    csrc[p] = es[e];
    cw[p] = ew[e];
}

// ===========================================================================
// HMMA GEMM: C[M x 512] = A[M x K] @ B^T[512 x K], bf16 3-term split
// CTA 128x128, BK=32, 256 threads, warp tile 64x32 (2m x 4n warps)
// 2-stage cp.async pipeline (R3-proven structure).
// Swizzle: 16B chunk c of row r at c ^ ((r>>1)&3) -> conflict-free for both
// cp.async stores and ldmatrix.x4 reads.
// ===========================================================================
#define STG 32768

__global__ __launch_bounds__(256)
void gemm_hmma_kernel(const __nv_bfloat16* __restrict__ Ah,
                      const __nv_bfloat16* __restrict__ Al, int lda,
                      const __nv_bfloat16* __restrict__ Bh,
                      const __nv_bfloat16* __restrict__ Bl, int ldb,
                      float* __restrict__ C, int ldc, int nkc)
{
    extern __shared__ char smem[];
    const uint32_t sb = smem_to_u32(smem);
    const int tid  = threadIdx.x;
    const int lane = tid & 31;
    const int wid  = tid >> 5;
    const int m0 = blockIdx.y * 128;
    const int n0 = blockIdx.x * 128;
    const int wm = (wid >> 2) * 64;
    const int wn = (wid & 3) * 32;

    float acc[4][4][4];
#pragma unroll
    for (int i = 0; i < 4; i++)
#pragma unroll
        for (int j = 0; j < 4; j++)
#pragma unroll
            for (int q = 0; q < 4; q++) acc[i][j][q] = 0.f;

    auto load_stage = [&](int kc, int s) {
        int kk = kc * 32;
#pragma unroll
        for (int j = 0; j < 8; j++) {
            int id = tid + j * 256;
            int tile = id >> 9;               // 0..3
            int r = (id >> 2) & 127;
            int c = id & 3;
            uint32_t soff = sb + s * STG + tile * 8192 + r * 64
                          + ((c ^ ((r >> 1) & 3)) << 4);
            const __nv_bfloat16* g;
            if (tile == 0)      g = Ah + (size_t)(m0 + r) * lda + kk + c * 8;
            else if (tile == 1) g = Al + (size_t)(m0 + r) * lda + kk + c * 8;
            else if (tile == 2) g = Bh + (size_t)(n0 + r) * ldb + kk + c * 8;
            else                g = Bl + (size_t)(n0 + r) * ldb + kk + c * 8;
            cp16(soff, g);
        }
        asm volatile("cp.async.commit_group;");
    };

    load_stage(0, 0);

    for (int kc = 0; kc < nkc; kc++) {
        int s = kc & 1;
        if (kc + 1 < nkc) {
            load_stage(kc + 1, s ^ 1);
            asm volatile("cp.async.wait_group 1;");
        } else {
            asm volatile("cp.async.wait_group 0;");
        }
        __syncthreads();

        uint32_t tAh = sb + s * STG;
        uint32_t tAl = tAh + 8192;
        uint32_t tBh = tAh + 16384;
        uint32_t tBl = tAh + 24576;

#pragma unroll
        for (int kh = 0; kh < 2; kh++) {
            uint32_t ah[4][4], al[4][4], bh[2][4], bl[2][4];
            const int rlo = lane & 15;
            const int q   = 2 * kh + (lane >> 4);
#pragma unroll
            for (int i = 0; i < 4; i++) {
                int r = wm + i * 16 + rlo;
                uint32_t off = r * 64 + ((q ^ ((r >> 1) & 3)) << 4);
                ldsm4(ah[i][0], ah[i][1], ah[i][2], ah[i][3], tAh + off);
                ldsm4(al[i][0], al[i][1], al[i][2], al[i][3], tAl + off);
            }
#pragma unroll
            for (int j = 0; j < 2; j++) {
                int r = wn + j * 16 + rlo;
                uint32_t off = r * 64 + ((q ^ ((r >> 1) & 3)) << 4);
                ldsm4(bh[j][0], bh[j][1], bh[j][2], bh[j][3], tBh + off);
                ldsm4(bl[j][0], bl[j][1], bl[j][2], bl[j][3], tBl + off);
            }
#pragma unroll
            for (int i = 0; i < 4; i++) {
#pragma unroll
                for (int jj = 0; jj < 4; jj++) {
                    uint32_t bh0 = bh[jj >> 1][jj & 1];
                    uint32_t bh1 = bh[jj >> 1][(jj & 1) + 2];
                    uint32_t bl0 = bl[jj >> 1][jj & 1];
                    uint32_t bl1 = bl[jj >> 1][(jj & 1) + 2];
                    mma16816(acc[i][jj], ah[i], bh0, bh1);
                    mma16816(acc[i][jj], ah[i], bl0, bl1);
                    mma16816(acc[i][jj], al[i], bh0, bh1);
                }
            }
        }
        __syncthreads();
    }

    // epilogue
#pragma unroll
    for (int i = 0; i < 4; i++) {
        int row = m0 + wm + i * 16 + (lane >> 2);
#pragma unroll
        for (int jj = 0; jj < 4; jj++) {
            int col = n0 + wn + jj * 8 + 2 * (lane & 3);
            float2 v0 = make_float2(acc[i][jj][0], acc[i][jj][1]);
            float2 v1 = make_float2(acc[i][jj][2], acc[i][jj][3]);
            *(float2*)(C + (size_t)row * ldc + col) = v0;
            *(float2*)(C + (size_t)(row + 8) * ldc + col) = v1;
        }
    }
}

// ===========================================================================
// Layer-1 CSR gather: h1 = relu(agg(src)+b1), written as bf16 hi/lo planes
// block = 128 threads per node; each thread owns 4 columns.
// ===========================================================================
__global__ __launch_bounds__(128)
void gather_kernel(const float* __restrict__ src, const int* __restrict__ ptr,
                   const int* __restrict__ cs, const float* __restrict__ cw,
                   const float* __restrict__ bias,
                   __nv_bfloat16* __restrict__ oh, __nv_bfloat16* __restrict__ ol)
{
    int node = blockIdx.x;
    int tid = threadIdx.x;
    int beg = ptr[node], end = ptr[node + 1];
    float a0 = 0.f, a1 = 0.f, a2 = 0.f, a3 = 0.f;
    const int c0 = tid, c1 = tid + 128, c2 = tid + 256, c3 = tid + 384;
    for (int i = beg; i < end; i++) {
        int s = cs[i];
        float w = cw[i];
        const float* ps = src + (size_t)s * HSTR;
        a0 = fmaf(w, ps[c0], a0);
        a1 = fmaf(w, ps[c1], a1);
        a2 = fmaf(w, ps[c2], a2);
        a3 = fmaf(w, ps[c3], a3);
    }
    float v0 = fmaxf(a0 + bias[c0], 0.f);
    float v1 = fmaxf(a1 + bias[c1], 0.f);
    float v2 = fmaxf(a2 + bias[c2], 0.f);
    float v3 = fmaxf(a3 + ((c3 < HID) ? bias[c3] : 0.f), 0.f);
    size_t base = (size_t)node * HSTR;
    __nv_bfloat16 h, l;
    split2(v0, h, l); oh[base + c0] = h; ol[base + c0] = l;
    split2(v1, h, l); oh[base + c1] = h; ol[base + c1] = l;
    split2(v2, h, l); oh[base + c2] = h; ol[base + c2] = l;
    split2(v3, h, l); oh[base + c3] = h; ol[base + c3] = l;
}

// ===========================================================================
// Layer-2 gather fused with W3 projection:
// h2 = relu(agg(src)+b2) (in registers), s1[node][0..5] = h2 @ w3.
// Skips materializing h2 (saves 100MB write + 100MB read + a launch).
// ===========================================================================
__global__ __launch_bounds__(128)
void gather_proj_kernel(const float* __restrict__ src, const int* __restrict__ ptr,
                        const int* __restrict__ cs, const float* __restrict__ cw,
                        const float* __restrict__ bias,
                        const float* __restrict__ w3,
                        float* __restrict__ s1)
{
    __shared__ float red[6][128];
    int node = blockIdx.x;
    int tid = threadIdx.x;
    int beg = ptr[node], end = ptr[node + 1];
    float a0 = 0.f, a1 = 0.f, a2 = 0.f, a3 = 0.f;
    const int c0 = tid, c1 = tid + 128, c2 = tid + 256, c3 = tid + 384;
    for (int i = beg; i < end; i++) {
        int s = cs[i];
        float w = cw[i];
        const float* ps = src + (size_t)s * HSTR;
        a0 = fmaf(w, ps[c0], a0);
        a1 = fmaf(w, ps[c1], a1);
        a2 = fmaf(w, ps[c2], a2);
        a3 = fmaf(w, ps[c3], a3);
    }
    float v0 = fmaxf(a0 + bias[c0], 0.f);
    float v1 = fmaxf(a1 + bias[c1], 0.f);
    float v2 = fmaxf(a2 + bias[c2], 0.f);
    float v3 = (c3 < HID) ? fmaxf(a3 + bias[c3], 0.f) : 0.f;

    float p[6] = {0.f, 0.f, 0.f, 0.f, 0.f, 0.f};
    const float* r0 = w3 + (size_t)c0 * 6;
    const float* r1 = w3 + (size_t)c1 * 6;
    const float* r2 = w3 + (size_t)c2 * 6;
#pragma unroll
    for (int j = 0; j < 6; j++) {
        float t = v0 * __ldg(&r0[j]) + v1 * __ldg(&r1[j]) + v2 * __ldg(&r2[j]);
        if (c3 < HID) t += v3 * __ldg(&w3[(size_t)c3 * 6 + j]);
        p[j] = t;
    }
#pragma unroll
    for (int j = 0; j < 6; j++) red[j][tid] = p[j];
    __syncthreads();
#pragma unroll
    for (int s = 64; s >= 1; s >>= 1) {
        if (tid < s) {
#pragma unroll
            for (int j = 0; j < 6; j++) red[j][tid] += red[j][tid + s];
        }
        __syncthreads();
    }
    if (tid < 6) s1[(size_t)node * 8 + tid] = red[tid][0];
}

// ===========================================================================
// Final fused: aggregate (CSR) + b3 + log_softmax, warp per node
// ===========================================================================
__global__ void final_kernel(const float* __restrict__ s1, const int* __restrict__ ptr,
                             const int* __restrict__ cs, const float* __restrict__ cw,
                             const float* __restrict__ b3, float* __restrict__ out, int M)
{
    int node = (blockIdx.x * blockDim.x + threadIdx.x) >> 5;
    int lane = threadIdx.x & 31;
    if (node >= M) return;
    int beg = ptr[node], end = ptr[node + 1];
    float a[6] = {0.f, 0.f, 0.f, 0.f, 0.f, 0.f};
    for (int i = beg + lane; i < end; i += 32) {
        int s = cs[i];
        float w = cw[i];
        const float* ps = s1 + (size_t)s * 8;
#pragma unroll
        for (int j = 0; j < 6; j++) a[j] = fmaf(w, ps[j], a[j]);
    }
#pragma unroll
    for (int j = 0; j < 6; j++)
#pragma unroll
        for (int off = 16; off > 0; off >>= 1)
            a[j] += __shfl_xor_sync(0xffffffffu, a[j], off);
    if (lane == 0) {
        float v[6];
#pragma unroll
        for (int j = 0; j < 6; j++) v[j] = a[j] + b3[j];
        float m = v[0];
#pragma unroll
        for (int j = 1; j < 6; j++) m = fmaxf(m, v[j]);
        float s = 0.f;
#pragma unroll
        for (int j = 0; j < 6; j++) s += __expf(v[j] - m);
        float l = logf(s) + m;
        float* po = out + (size_t)node * 6;
#pragma unroll
        for (int j = 0; j < 6; j++) po[j] = v[j] - l;
    }
}

// ===========================================================================
// Launch
// ===========================================================================
extern "C" void kernel_launch(void* const* d_in, const int* in_sizes, int n_in,
                              void* d_out, int out_size)
{
    const float* x   = (const float*)d_in[0];
    const float* w1  = (const float*)d_in[1];
    const float* b1  = (const float*)d_in[2];
    const float* w2  = (const float*)d_in[3];
    const float* b2  = (const float*)d_in[4];
    const float* w3  = (const float*)d_in[5];
    const float* b3  = (const float*)d_in[6];
    const float* ew  = (const float*)d_in[7];
    const int*   es  = (const int*)d_in[8];
    const int*   ed  = (const int*)d_in[9];
    float* out = (float*)d_out;

    const int E = in_sizes[7];

    __nv_bfloat16 *xhi, *xlo, *w1hi, *w1lo, *w2hi, *w2lo, *hhi, *hlo;
    float *pa, *ps1, *cwv;
    int *cnt, *part, *aux, *ptr, *wp, *csrc;
    cudaGetSymbolAddress((void**)&xhi,  g_xhi);
    cudaGetSymbolAddress((void**)&xlo,  g_xlo);
    cudaGetSymbolAddress((void**)&w1hi, g_w1hi);
    cudaGetSymbolAddress((void**)&w1lo, g_w1lo);
    cudaGetSymbolAddress((void**)&w2hi, g_w2hi);
    cudaGetSymbolAddress((void**)&w2lo, g_w2lo);
    cudaGetSymbolAddress((void**)&hhi,  g_hhi);
    cudaGetSymbolAddress((void**)&hlo,  g_hlo);
    cudaGetSymbolAddress((void**)&pa,   g_a);
    cudaGetSymbolAddress((void**)&ps1,  g_s1);
    cudaGetSymbolAddress((void**)&cnt,  g_cnt);
    cudaGetSymbolAddress((void**)&part, g_part);
    cudaGetSymbolAddress((void**)&aux,  g_aux);
    cudaGetSymbolAddress((void**)&ptr,  g_ptr);
    cudaGetSymbolAddress((void**)&wp,   g_wp);
    cudaGetSymbolAddress((void**)&csrc, g_csrc);
    cudaGetSymbolAddress((void**)&cwv,  g_cw);

    cudaFuncSetAttribute(gemm_hmma_kernel,
                         cudaFuncAttributeMaxDynamicSharedMemorySize, 2 * STG);

    dim3 ggrid(HSTR / 128, NNP / 128);   // (4, 391), N fastest for A L2 reuse

    // ---- input prep (gemm1 stays launch #4 for ncu) ----
    {
        int total = NN * XCHUNKS;
        split_x_kernel<<<(total + 255) / 256, 256>>>(x, xhi, xlo);           // #1
    }
    prep_w_kernel<<<(HSTR * INDP + 255) / 256, 256>>>(w1, w1hi, w1lo,
                                                      IND, HID, INDP, HSTR); // #2
    prep_w_kernel<<<(HSTR * HSTR + 255) / 256, 256>>>(w2, w2hi, w2lo,
                                                      HID, HID, HSTR, HSTR); // #3

    // ---- Layer 1 GEMM ----                                                // #4
    gemm_hmma_kernel<<<ggrid, 256, 2 * STG>>>(xhi, xlo, INDP, w1hi, w1lo, INDP,
                                              pa, HSTR, INDP / 32);

    // ---- CSR build ----
    cnt_zero_kernel<<<(NNP + 255) / 256, 256>>>(cnt);
    hist_kernel<<<(E + 255) / 256, 256>>>(ed, cnt, E);
    {
        int nb = (NN + 255) / 256;   // 196
        scan1_kernel<<<nb, 256>>>(cnt, part, aux, NN);
        scan2_kernel<<<1, 256>>>(aux, nb);
        scan3_kernel<<<nb, 256>>>(part, aux, ptr, wp, NN, E);
    }
    fill_kernel<<<(E + 255) / 256, 256>>>(es, ed, ew, wp, csrc, cwv, E);

    // ---- Layer 1 aggregate ----
    gather_kernel<<<NN, 128>>>(pa, ptr, csrc, cwv, b1, hhi, hlo);

    // ---- Layer 2 GEMM + fused aggregate/projection ----
    gemm_hmma_kernel<<<ggrid, 256, 2 * STG>>>(hhi, hlo, HSTR, w2hi, w2lo, HSTR,
                                              pa, HSTR, HSTR / 32);
    gather_proj_kernel<<<NN, 128>>>(pa, ptr, csrc, cwv, b2, w3, ps1);

    // ---- Layer 3 aggregate + log_softmax ----
    final_kernel<<<(NN + 7) / 8, 256>>>(ps1, ptr, csrc, cwv, b3, out, NN);

    (void)n_in; (void)out_size;
}

// round 6
// speedup vs baseline: 1.4944x; 1.0068x over previous
#include <cuda_runtime.h>
#include <cuda_bf16.h>
#include <math.h>
#include <stdint.h>

// ===========================================================================
// Problem constants (fixed shapes)
// ===========================================================================
#define NN     50000          // nodes
#define NNP    50048          // padded to 128
#define IND    3703           // input dim
#define INDP   3712           // padded to 64
#define HID    500
#define HSTR   512            // padded hidden
#define EMAX   1000000

// ===========================================================================
// Device scratch (static globals; no dynamic allocation)
// ===========================================================================
__device__ __nv_bfloat16 g_xhi[(size_t)NNP * INDP];
__device__ __nv_bfloat16 g_xlo[(size_t)NNP * INDP];
__device__ __nv_bfloat16 g_w1hi[HSTR * INDP];
__device__ __nv_bfloat16 g_w1lo[HSTR * INDP];
__device__ __nv_bfloat16 g_w2hi[HSTR * HSTR];
__device__ __nv_bfloat16 g_w2lo[HSTR * HSTR];
__device__ __nv_bfloat16 g_hhi[(size_t)NNP * HSTR];
__device__ __nv_bfloat16 g_hlo[(size_t)NNP * HSTR];
__device__ float g_a[(size_t)NNP * HSTR];    // GEMM output
__device__ float g_s1[(size_t)NNP * 8];      // layer-3 per-node logits (pre-agg)

__device__ int   g_cnt[NNP];
__device__ int   g_part[NNP];
__device__ int   g_aux[256];
__device__ int   g_ptr[NN + 1];
__device__ int   g_wp[NNP];
__device__ int   g_csrc[EMAX];
__device__ float g_cw[EMAX];

// ===========================================================================
// Helpers
// ===========================================================================
__device__ __forceinline__ uint32_t smem_to_u32(const void* p) {
    uint32_t a;
    asm("{ .reg .u64 t; cvta.to.shared.u64 t, %1; cvt.u32.u64 %0, t; }"
        : "=r"(a) : "l"(p));
    return a;
}
__device__ __forceinline__ void ldsm4(uint32_t& r0, uint32_t& r1,
                                      uint32_t& r2, uint32_t& r3, uint32_t addr) {
    asm volatile("ldmatrix.sync.aligned.m8n8.x4.shared.b16 {%0,%1,%2,%3}, [%4];"
        : "=r"(r0), "=r"(r1), "=r"(r2), "=r"(r3) : "r"(addr));
}
__device__ __forceinline__ void mma16816(float* c, const uint32_t* a,
                                         uint32_t b0, uint32_t b1) {
    asm volatile("mma.sync.aligned.m16n8k16.row.col.f32.bf16.bf16.f32 "
        "{%0,%1,%2,%3}, {%4,%5,%6,%7}, {%8,%9}, {%0,%1,%2,%3};"
        : "+f"(c[0]), "+f"(c[1]), "+f"(c[2]), "+f"(c[3])
        : "r"(a[0]), "r"(a[1]), "r"(a[2]), "r"(a[3]), "r"(b0), "r"(b1));
}
__device__ __forceinline__ void cp16(uint32_t soff, const void* g) {
    asm volatile("cp.async.cg.shared.global [%0], [%1], 16;" :: "r"(soff), "l"(g));
}

__device__ __forceinline__ void split2(float v, __nv_bfloat16& h, __nv_bfloat16& l) {
    h = __float2bfloat16_rn(v);
    l = __float2bfloat16_rn(v - __bfloat162float(h));
}
__device__ __forceinline__ uint32_t pk(__nv_bfloat16 a, __nv_bfloat16 b) {
    return (uint32_t)__bfloat16_as_ushort(a) | ((uint32_t)__bfloat16_as_ushort(b) << 16);
}

// ===========================================================================
// X -> bf16 hi/lo split
// ===========================================================================
#define XCHUNKS (INDP / 8)   // 464
__global__ __launch_bounds__(256)
void split_x_kernel(const float* __restrict__ x,
                    __nv_bfloat16* __restrict__ xh, __nv_bfloat16* __restrict__ xl)
{
    int idx = blockIdx.x * 256 + threadIdx.x;
    int total = NN * XCHUNKS;
    if (idx >= total) return;
    int row = idx / XCHUNKS;
    int cb  = (idx - row * XCHUNKS) * 8;
    const float* px = x + (size_t)row * IND;
    __nv_bfloat16 hh[8], ll[8];
#pragma unroll
    for (int j = 0; j < 8; j++) {
        int c = cb + j;
        float v = (c < IND) ? px[c] : 0.f;
        split2(v, hh[j], ll[j]);
    }
    size_t off = (size_t)row * INDP + cb;
    uint4 uh, ul;
    uh.x = pk(hh[0], hh[1]); uh.y = pk(hh[2], hh[3]);
    uh.z = pk(hh[4], hh[5]); uh.w = pk(hh[6], hh[7]);
    ul.x = pk(ll[0], ll[1]); ul.y = pk(ll[2], ll[3]);
    ul.z = pk(ll[4], ll[5]); ul.w = pk(ll[6], ll[7]);
    *(uint4*)(xh + off) = uh;
    *(uint4*)(xl + off) = ul;
}

// ===========================================================================
// Weight prep (coalesced transpose): w [K x N] fp32 -> hi/lo [NP][KP] bf16.
// 32x32 tile through padded smem; both gmem read & write coalesced.
// ===========================================================================
__global__ __launch_bounds__(256)
void prep_w_kernel(const float* __restrict__ w,
                   __nv_bfloat16* __restrict__ dh,
                   __nv_bfloat16* __restrict__ dl,
                   int K, int N, int KP, int NP)
{
    __shared__ float t[32][33];
    int kb = blockIdx.x * 32;
    int nb = blockIdx.y * 32;
    int tx = threadIdx.x & 31;
    int ty = threadIdx.x >> 5;     // 0..7
#pragma unroll
    for (int i = ty; i < 32; i += 8) {
        int k = kb + i, n = nb + tx;
        t[i][tx] = (k < K && n < N) ? w[(size_t)k * N + n] : 0.f;
    }
    __syncthreads();
#pragma unroll
    for (int i = ty; i < 32; i += 8) {
        int n = nb + i, k = kb + tx;
        if (n < NP && k < KP) {
            __nv_bfloat16 h, l;
            split2(t[tx][i], h, l);
            size_t o = (size_t)n * KP + k;
            dh[o] = h; dl[o] = l;
        }
    }
}

// ===========================================================================
// CSR build
// ===========================================================================
__global__ void cnt_zero_kernel(int* __restrict__ cnt) {
    int i = blockIdx.x * 256 + threadIdx.x;
    if (i < NNP) cnt[i] = 0;
}
__global__ void hist_kernel(const int* __restrict__ ed, int* __restrict__ cnt, int E) {
    int e = blockIdx.x * 256 + threadIdx.x;
    if (e < E) atomicAdd(&cnt[ed[e]], 1);
}
__global__ void scan1_kernel(const int* __restrict__ cnt, int* __restrict__ part,
                             int* __restrict__ aux, int n)
{
    __shared__ int s[256];
    int tid = threadIdx.x;
    int g = blockIdx.x * 256 + tid;
    int v = (g < n) ? cnt[g] : 0;
    s[tid] = v;
    __syncthreads();
#pragma unroll
    for (int o = 1; o < 256; o <<= 1) {
        int t = (tid >= o) ? s[tid - o] : 0;
        __syncthreads();
        s[tid] += t;
        __syncthreads();
    }
    if (g < n) part[g] = s[tid] - v;
    if (tid == 255) aux[blockIdx.x] = s[tid];
}
__global__ void scan2_kernel(int* __restrict__ aux, int nb)
{
    __shared__ int s[256];
    int tid = threadIdx.x;
    int v = (tid < nb) ? aux[tid] : 0;
    s[tid] = v;
    __syncthreads();
#pragma unroll
    for (int o = 1; o < 256; o <<= 1) {
        int t = (tid >= o) ? s[tid - o] : 0;
        __syncthreads();
        s[tid] += t;
        __syncthreads();
    }
    if (tid < nb) aux[tid] = s[tid] - v;   // exclusive
}
__global__ void scan3_kernel(const int* __restrict__ part, const int* __restrict__ aux,
                             int* __restrict__ ptr, int* __restrict__ wp, int n, int E)
{
    int g = blockIdx.x * 256 + threadIdx.x;
    if (g < n) {
        int v = part[g] + aux[g >> 8];
        ptr[g] = v;
        wp[g] = v;
    }
    if (g == 0) ptr[n] = E;
}
__global__ void fill_kernel(const int* __restrict__ es, const int* __restrict__ ed,
                            const float* __restrict__ ew, int* __restrict__ wp,
                            int* __restrict__ csrc, float* __restrict__ cw, int E)
{
    int e = blockIdx.x * 256 + threadIdx.x;
    if (e >= E) return;
    int d = ed[e];
    int p = atomicAdd(&wp[d], 1);
    csrc[p] = es[e];
    cw[p] = ew[e];
}

// ===========================================================================
// HMMA GEMM: C[M x 512] = A[M x K] @ B^T[512 x K], bf16 3-term split
// CTA 128x128, BK=32, 256 threads, warp tile 64x32 (2m x 4n warps)
// 2-stage cp.async pipeline (R3/R5-proven structure — DO NOT TOUCH).
// ===========================================================================
#define STG 32768

__global__ __launch_bounds__(256)
void gemm_hmma_kernel(const __nv_bfloat16* __restrict__ Ah,
                      const __nv_bfloat16* __restrict__ Al, int lda,
                      const __nv_bfloat16* __restrict__ Bh,
                      const __nv_bfloat16* __restrict__ Bl, int ldb,
                      float* __restrict__ C, int ldc, int nkc)
{
    extern __shared__ char smem[];
    const uint32_t sb = smem_to_u32(smem);
    const int tid  = threadIdx.x;
    const int lane = tid & 31;
    const int wid  = tid >> 5;
    const int m0 = blockIdx.y * 128;
    const int n0 = blockIdx.x * 128;
    const int wm = (wid >> 2) * 64;
    const int wn = (wid & 3) * 32;

    float acc[4][4][4];
#pragma unroll
    for (int i = 0; i < 4; i++)
#pragma unroll
        for (int j = 0; j < 4; j++)
#pragma unroll
            for (int q = 0; q < 4; q++) acc[i][j][q] = 0.f;

    auto load_stage = [&](int kc, int s) {
        int kk = kc * 32;
#pragma unroll
        for (int j = 0; j < 8; j++) {
            int id = tid + j * 256;
            int tile = id >> 9;               // 0..3
            int r = (id >> 2) & 127;
            int c = id & 3;
            uint32_t soff = sb + s * STG + tile * 8192 + r * 64
                          + ((c ^ ((r >> 1) & 3)) << 4);
            const __nv_bfloat16* g;
            if (tile == 0)      g = Ah + (size_t)(m0 + r) * lda + kk + c * 8;
            else if (tile == 1) g = Al + (size_t)(m0 + r) * lda + kk + c * 8;
            else if (tile == 2) g = Bh + (size_t)(n0 + r) * ldb + kk + c * 8;
            else                g = Bl + (size_t)(n0 + r) * ldb + kk + c * 8;
            cp16(soff, g);
        }
        asm volatile("cp.async.commit_group;");
    };

    load_stage(0, 0);

    for (int kc = 0; kc < nkc; kc++) {
        int s = kc & 1;
        if (kc + 1 < nkc) {
            load_stage(kc + 1, s ^ 1);
            asm volatile("cp.async.wait_group 1;");
        } else {
            asm volatile("cp.async.wait_group 0;");
        }
        __syncthreads();

        uint32_t tAh = sb + s * STG;
        uint32_t tAl = tAh + 8192;
        uint32_t tBh = tAh + 16384;
        uint32_t tBl = tAh + 24576;

#pragma unroll
        for (int kh = 0; kh < 2; kh++) {
            uint32_t ah[4][4], al[4][4], bh[2][4], bl[2][4];
            const int rlo = lane & 15;
            const int q   = 2 * kh + (lane >> 4);
#pragma unroll
            for (int i = 0; i < 4; i++) {
                int r = wm + i * 16 + rlo;
                uint32_t off = r * 64 + ((q ^ ((r >> 1) & 3)) << 4);
                ldsm4(ah[i][0], ah[i][1], ah[i][2], ah[i][3], tAh + off);
                ldsm4(al[i][0], al[i][1], al[i][2], al[i][3], tAl + off);
            }
#pragma unroll
            for (int j = 0; j < 2; j++) {
                int r = wn + j * 16 + rlo;
                uint32_t off = r * 64 + ((q ^ ((r >> 1) & 3)) << 4);
                ldsm4(bh[j][0], bh[j][1], bh[j][2], bh[j][3], tBh + off);
                ldsm4(bl[j][0], bl[j][1], bl[j][2], bl[j][3], tBl + off);
            }
#pragma unroll
            for (int i = 0; i < 4; i++) {
#pragma unroll
                for (int jj = 0; jj < 4; jj++) {
                    uint32_t bh0 = bh[jj >> 1][jj & 1];
                    uint32_t bh1 = bh[jj >> 1][(jj & 1) + 2];
                    uint32_t bl0 = bl[jj >> 1][jj & 1];
                    uint32_t bl1 = bl[jj >> 1][(jj & 1) + 2];
                    mma16816(acc[i][jj], ah[i], bh0, bh1);
                    mma16816(acc[i][jj], ah[i], bl0, bl1);
                    mma16816(acc[i][jj], al[i], bh0, bh1);
                }
            }
        }
        __syncthreads();
    }

    // epilogue
#pragma unroll
    for (int i = 0; i < 4; i++) {
        int row = m0 + wm + i * 16 + (lane >> 2);
#pragma unroll
        for (int jj = 0; jj < 4; jj++) {
            int col = n0 + wn + jj * 8 + 2 * (lane & 3);
            float2 v0 = make_float2(acc[i][jj][0], acc[i][jj][1]);
            float2 v1 = make_float2(acc[i][jj][2], acc[i][jj][3]);
            *(float2*)(C + (size_t)row * ldc + col) = v0;
            *(float2*)(C + (size_t)(row + 8) * ldc + col) = v1;
        }
    }
}

// ===========================================================================
// Layer-1 CSR gather: h1 = relu(agg(src)+b1) -> bf16 hi/lo planes.
// 2-way edge unroll: two independent accumulator sets double memory-level
// parallelism (breaks the per-edge FMA RAW chain on L2-latency-bound loop).
// ===========================================================================
__global__ __launch_bounds__(128)
void gather_kernel(const float* __restrict__ src, const int* __restrict__ ptr,
                   const int* __restrict__ cs, const float* __restrict__ cw,
                   const float* __restrict__ bias,
                   __nv_bfloat16* __restrict__ oh, __nv_bfloat16* __restrict__ ol)
{
    int node = blockIdx.x;
    int tid = threadIdx.x;
    int beg = ptr[node], end = ptr[node + 1];
    const int c0 = tid, c1 = tid + 128, c2 = tid + 256, c3 = tid + 384;
    float a0 = 0.f, a1 = 0.f, a2 = 0.f, a3 = 0.f;
    float e0 = 0.f, e1 = 0.f, e2 = 0.f, e3 = 0.f;
    int i = beg;
    for (; i + 1 < end; i += 2) {
        int sA = cs[i],     sB = cs[i + 1];
        float wA = cw[i],   wB = cw[i + 1];
        const float* pA = src + (size_t)sA * HSTR;
        const float* pB = src + (size_t)sB * HSTR;
        a0 = fmaf(wA, pA[c0], a0);  e0 = fmaf(wB, pB[c0], e0);
        a1 = fmaf(wA, pA[c1], a1);  e1 = fmaf(wB, pB[c1], e1);
        a2 = fmaf(wA, pA[c2], a2);  e2 = fmaf(wB, pB[c2], e2);
        a3 = fmaf(wA, pA[c3], a3);  e3 = fmaf(wB, pB[c3], e3);
    }
    if (i < end) {
        int s = cs[i]; float w = cw[i];
        const float* ps = src + (size_t)s * HSTR;
        a0 = fmaf(w, ps[c0], a0);
        a1 = fmaf(w, ps[c1], a1);
        a2 = fmaf(w, ps[c2], a2);
        a3 = fmaf(w, ps[c3], a3);
    }
    a0 += e0; a1 += e1; a2 += e2; a3 += e3;
    float v0 = fmaxf(a0 + bias[c0], 0.f);
    float v1 = fmaxf(a1 + bias[c1], 0.f);
    float v2 = fmaxf(a2 + bias[c2], 0.f);
    float v3 = fmaxf(a3 + ((c3 < HID) ? bias[c3] : 0.f), 0.f);
    size_t base = (size_t)node * HSTR;
    __nv_bfloat16 h, l;
    split2(v0, h, l); oh[base + c0] = h; ol[base + c0] = l;
    split2(v1, h, l); oh[base + c1] = h; ol[base + c1] = l;
    split2(v2, h, l); oh[base + c2] = h; ol[base + c2] = l;
    split2(v3, h, l); oh[base + c3] = h; ol[base + c3] = l;
}

// ===========================================================================
// Layer-2 gather fused with W3 projection (2-way edge unroll):
// h2 = relu(agg(src)+b2) in registers, s1[node][0..5] = h2 @ w3.
// ===========================================================================
__global__ __launch_bounds__(128)
void gather_proj_kernel(const float* __restrict__ src, const int* __restrict__ ptr,
                        const int* __restrict__ cs, const float* __restrict__ cw,
                        const float* __restrict__ bias,
                        const float* __restrict__ w3,
                        float* __restrict__ s1)
{
    __shared__ float red[6][128];
    int node = blockIdx.x;
    int tid = threadIdx.x;
    int beg = ptr[node], end = ptr[node + 1];
    const int c0 = tid, c1 = tid + 128, c2 = tid + 256, c3 = tid + 384;
    float a0 = 0.f, a1 = 0.f, a2 = 0.f, a3 = 0.f;
    float e0 = 0.f, e1 = 0.f, e2 = 0.f, e3 = 0.f;
    int i = beg;
    for (; i + 1 < end; i += 2) {
        int sA = cs[i],     sB = cs[i + 1];
        float wA = cw[i],   wB = cw[i + 1];
        const float* pA = src + (size_t)sA * HSTR;
        const float* pB = src + (size_t)sB * HSTR;
        a0 = fmaf(wA, pA[c0], a0);  e0 = fmaf(wB, pB[c0], e0);
        a1 = fmaf(wA, pA[c1], a1);  e1 = fmaf(wB, pB[c1], e1);
        a2 = fmaf(wA, pA[c2], a2);  e2 = fmaf(wB, pB[c2], e2);
        a3 = fmaf(wA, pA[c3], a3);  e3 = fmaf(wB, pB[c3], e3);
    }
    if (i < end) {
        int s = cs[i]; float w = cw[i];
        const float* ps = src + (size_t)s * HSTR;
        a0 = fmaf(w, ps[c0], a0);
        a1 = fmaf(w, ps[c1], a1);
        a2 = fmaf(w, ps[c2], a2);
        a3 = fmaf(w, ps[c3], a3);
    }
    a0 += e0; a1 += e1; a2 += e2; a3 += e3;
    float v0 = fmaxf(a0 + bias[c0], 0.f);
    float v1 = fmaxf(a1 + bias[c1], 0.f);
    float v2 = fmaxf(a2 + bias[c2], 0.f);
    float v3 = (c3 < HID) ? fmaxf(a3 + bias[c3], 0.f) : 0.f;

    float p[6] = {0.f, 0.f, 0.f, 0.f, 0.f, 0.f};
    const float* r0 = w3 + (size_t)c0 * 6;
    const float* r1 = w3 + (size_t)c1 * 6;
    const float* r2 = w3 + (size_t)c2 * 6;
#pragma unroll
    for (int j = 0; j < 6; j++) {
        float t = v0 * __ldg(&r0[j]) + v1 * __ldg(&r1[j]) + v2 * __ldg(&r2[j]);
        if (c3 < HID) t += v3 * __ldg(&w3[(size_t)c3 * 6 + j]);
        p[j] = t;
    }
#pragma unroll
    for (int j = 0; j < 6; j++) red[j][tid] = p[j];
    __syncthreads();
#pragma unroll
    for (int s = 64; s >= 1; s >>= 1) {
        if (tid < s) {
#pragma unroll
            for (int j = 0; j < 6; j++) red[j][tid] += red[j][tid + s];
        }
        __syncthreads();
    }
    if (tid < 6) s1[(size_t)node * 8 + tid] = red[tid][0];
}

// ===========================================================================
// Final fused: aggregate (CSR) + b3 + log_softmax, warp per node
// ===========================================================================
__global__ void final_kernel(const float* __restrict__ s1, const int* __restrict__ ptr,
                             const int* __restrict__ cs, const float* __restrict__ cw,
                             const float* __restrict__ b3, float* __restrict__ out, int M)
{
    int node = (blockIdx.x * blockDim.x + threadIdx.x) >> 5;
    int lane = threadIdx.x & 31;
    if (node >= M) return;
    int beg = ptr[node], end = ptr[node + 1];
    float a[6] = {0.f, 0.f, 0.f, 0.f, 0.f, 0.f};
    for (int i = beg + lane; i < end; i += 32) {
        int s = cs[i];
        float w = cw[i];
        const float* ps = s1 + (size_t)s * 8;
#pragma unroll
        for (int j = 0; j < 6; j++) a[j] = fmaf(w, ps[j], a[j]);
    }
#pragma unroll
    for (int j = 0; j < 6; j++)
#pragma unroll
        for (int off = 16; off > 0; off >>= 1)
            a[j] += __shfl_xor_sync(0xffffffffu, a[j], off);
    if (lane == 0) {
        float v[6];
#pragma unroll
        for (int j = 0; j < 6; j++) v[j] = a[j] + b3[j];
        float m = v[0];
#pragma unroll
        for (int j = 1; j < 6; j++) m = fmaxf(m, v[j]);
        float s = 0.f;
#pragma unroll
        for (int j = 0; j < 6; j++) s += __expf(v[j] - m);
        float l = logf(s) + m;
        float* po = out + (size_t)node * 6;
#pragma unroll
        for (int j = 0; j < 6; j++) po[j] = v[j] - l;
    }
}

// ===========================================================================
// Launch
// ===========================================================================
extern "C" void kernel_launch(void* const* d_in, const int* in_sizes, int n_in,
                              void* d_out, int out_size)
{
    const float* x   = (const float*)d_in[0];
    const float* w1  = (const float*)d_in[1];
    const float* b1  = (const float*)d_in[2];
    const float* w2  = (const float*)d_in[3];
    const float* b2  = (const float*)d_in[4];
    const float* w3  = (const float*)d_in[5];
    const float* b3  = (const float*)d_in[6];
    const float* ew  = (const float*)d_in[7];
    const int*   es  = (const int*)d_in[8];
    const int*   ed  = (const int*)d_in[9];
    float* out = (float*)d_out;

    const int E = in_sizes[7];

    __nv_bfloat16 *xhi, *xlo, *w1hi, *w1lo, *w2hi, *w2lo, *hhi, *hlo;
    float *pa, *ps1, *cwv;
    int *cnt, *part, *aux, *ptr, *wp, *csrc;
    cudaGetSymbolAddress((void**)&xhi,  g_xhi);
    cudaGetSymbolAddress((void**)&xlo,  g_xlo);
    cudaGetSymbolAddress((void**)&w1hi, g_w1hi);
    cudaGetSymbolAddress((void**)&w1lo, g_w1lo);
    cudaGetSymbolAddress((void**)&w2hi, g_w2hi);
    cudaGetSymbolAddress((void**)&w2lo, g_w2lo);
    cudaGetSymbolAddress((void**)&hhi,  g_hhi);
    cudaGetSymbolAddress((void**)&hlo,  g_hlo);
    cudaGetSymbolAddress((void**)&pa,   g_a);
    cudaGetSymbolAddress((void**)&ps1,  g_s1);
    cudaGetSymbolAddress((void**)&cnt,  g_cnt);
    cudaGetSymbolAddress((void**)&part, g_part);
    cudaGetSymbolAddress((void**)&aux,  g_aux);
    cudaGetSymbolAddress((void**)&ptr,  g_ptr);
    cudaGetSymbolAddress((void**)&wp,   g_wp);
    cudaGetSymbolAddress((void**)&csrc, g_csrc);
    cudaGetSymbolAddress((void**)&cwv,  g_cw);

    cudaFuncSetAttribute(gemm_hmma_kernel,
                         cudaFuncAttributeMaxDynamicSharedMemorySize, 2 * STG);

    dim3 ggrid(HSTR / 128, NNP / 128);   // (4, 391), N fastest for A L2 reuse

    // ---- input prep (gemm1 stays launch #4 for ncu) ----
    {
        int total = NN * XCHUNKS;
        split_x_kernel<<<(total + 255) / 256, 256>>>(x, xhi, xlo);           // #1
    }
    {
        dim3 g1((INDP + 31) / 32, (HSTR + 31) / 32);
        prep_w_kernel<<<g1, 256>>>(w1, w1hi, w1lo, IND, HID, INDP, HSTR);    // #2
        dim3 g2((HSTR + 31) / 32, (HSTR + 31) / 32);
        prep_w_kernel<<<g2, 256>>>(w2, w2hi, w2lo, HID, HID, HSTR, HSTR);    // #3
    }

    // ---- Layer 1 GEMM ----                                                // #4
    gemm_hmma_kernel<<<ggrid, 256, 2 * STG>>>(xhi, xlo, INDP, w1hi, w1lo, INDP,
                                              pa, HSTR, INDP / 32);

    // ---- CSR build ----
    cnt_zero_kernel<<<(NNP + 255) / 256, 256>>>(cnt);
    hist_kernel<<<(E + 255) / 256, 256>>>(ed, cnt, E);
    {
        int nb = (NN + 255) / 256;   // 196
        scan1_kernel<<<nb, 256>>>(cnt, part, aux, NN);
        scan2_kernel<<<1, 256>>>(aux, nb);
        scan3_kernel<<<nb, 256>>>(part, aux, ptr, wp, NN, E);
    }
    fill_kernel<<<(E + 255) / 256, 256>>>(es, ed, ew, wp, csrc, cwv, E);

    // ---- Layer 1 aggregate ----
    gather_kernel<<<NN, 128>>>(pa, ptr, csrc, cwv, b1, hhi, hlo);

    // ---- Layer 2 GEMM + fused aggregate/projection ----
    gemm_hmma_kernel<<<ggrid, 256, 2 * STG>>>(hhi, hlo, HSTR, w2hi, w2lo, HSTR,
                                              pa, HSTR, HSTR / 32);
    gather_proj_kernel<<<NN, 128>>>(pa, ptr, csrc, cwv, b2, w3, ps1);

    // ---- Layer 3 aggregate + log_softmax ----
    final_kernel<<<(NN + 7) / 8, 256>>>(ps1, ptr, csrc, cwv, b3, out, NN);

    (void)n_in; (void)out_size;
}

// round 7
// speedup vs baseline: 1.5239x; 1.0197x over previous
#include <cuda_runtime.h>
#include <cuda_bf16.h>
#include <cuda_fp16.h>
#include <math.h>
#include <stdint.h>

// ===========================================================================
// Problem constants (fixed shapes)
// ===========================================================================
#define NN     50000          // nodes
#define NNP    50048          // padded to 128
#define IND    3703           // input dim
#define INDP   3712           // padded to 64
#define HID    500
#define HSTR   512            // padded hidden
#define EMAX   1000000

// ===========================================================================
// Device scratch (static globals; no dynamic allocation)
// ===========================================================================
__device__ __nv_bfloat16 g_xhi[(size_t)NNP * INDP];
__device__ __nv_bfloat16 g_xlo[(size_t)NNP * INDP];
__device__ __nv_bfloat16 g_w1hi[HSTR * INDP];
__device__ __nv_bfloat16 g_w1lo[HSTR * INDP];
__device__ __nv_bfloat16 g_w2hi[HSTR * HSTR];
__device__ __nv_bfloat16 g_w2lo[HSTR * HSTR];
__device__ __nv_bfloat16 g_hhi[(size_t)NNP * HSTR];
__device__ __nv_bfloat16 g_hlo[(size_t)NNP * HSTR];
__device__ __half g_z[(size_t)NNP * HSTR];   // GEMM output (fp16 halves traffic)
__device__ float g_s1[(size_t)NNP * 8];      // layer-3 per-node logits (pre-agg)

__device__ int   g_cnt[NNP];
__device__ int   g_part[NNP];
__device__ int   g_aux[256];
__device__ int   g_ptr[NN + 1];
__device__ int   g_wp[NNP];
__device__ int   g_csrc[EMAX];
__device__ float g_cw[EMAX];

// ===========================================================================
// Helpers
// ===========================================================================
__device__ __forceinline__ uint32_t smem_to_u32(const void* p) {
    uint32_t a;
    asm("{ .reg .u64 t; cvta.to.shared.u64 t, %1; cvt.u32.u64 %0, t; }"
        : "=r"(a) : "l"(p));
    return a;
}
__device__ __forceinline__ void ldsm4(uint32_t& r0, uint32_t& r1,
                                      uint32_t& r2, uint32_t& r3, uint32_t addr) {
    asm volatile("ldmatrix.sync.aligned.m8n8.x4.shared.b16 {%0,%1,%2,%3}, [%4];"
        : "=r"(r0), "=r"(r1), "=r"(r2), "=r"(r3) : "r"(addr));
}
__device__ __forceinline__ void mma16816(float* c, const uint32_t* a,
                                         uint32_t b0, uint32_t b1) {
    asm volatile("mma.sync.aligned.m16n8k16.row.col.f32.bf16.bf16.f32 "
        "{%0,%1,%2,%3}, {%4,%5,%6,%7}, {%8,%9}, {%0,%1,%2,%3};"
        : "+f"(c[0]), "+f"(c[1]), "+f"(c[2]), "+f"(c[3])
        : "r"(a[0]), "r"(a[1]), "r"(a[2]), "r"(a[3]), "r"(b0), "r"(b1));
}
__device__ __forceinline__ void cp16(uint32_t soff, const void* g) {
    asm volatile("cp.async.cg.shared.global [%0], [%1], 16;" :: "r"(soff), "l"(g));
}

__device__ __forceinline__ void split2(float v, __nv_bfloat16& h, __nv_bfloat16& l) {
    h = __float2bfloat16_rn(v);
    l = __float2bfloat16_rn(v - __bfloat162float(h));
}
__device__ __forceinline__ uint32_t pk(__nv_bfloat16 a, __nv_bfloat16 b) {
    return (uint32_t)__bfloat16_as_ushort(a) | ((uint32_t)__bfloat16_as_ushort(b) << 16);
}

// ===========================================================================
// X -> bf16 hi/lo split
// ===========================================================================
#define XCHUNKS (INDP / 8)   // 464
__global__ __launch_bounds__(256)
void split_x_kernel(const float* __restrict__ x,
                    __nv_bfloat16* __restrict__ xh, __nv_bfloat16* __restrict__ xl)
{
    int idx = blockIdx.x * 256 + threadIdx.x;
    int total = NN * XCHUNKS;
    if (idx >= total) return;
    int row = idx / XCHUNKS;
    int cb  = (idx - row * XCHUNKS) * 8;
    const float* px = x + (size_t)row * IND;
    __nv_bfloat16 hh[8], ll[8];
#pragma unroll
    for (int j = 0; j < 8; j++) {
        int c = cb + j;
        float v = (c < IND) ? px[c] : 0.f;
        split2(v, hh[j], ll[j]);
    }
    size_t off = (size_t)row * INDP + cb;
    uint4 uh, ul;
    uh.x = pk(hh[0], hh[1]); uh.y = pk(hh[2], hh[3]);
    uh.z = pk(hh[4], hh[5]); uh.w = pk(hh[6], hh[7]);
    ul.x = pk(ll[0], ll[1]); ul.y = pk(ll[2], ll[3]);
    ul.z = pk(ll[4], ll[5]); ul.w = pk(ll[6], ll[7]);
    *(uint4*)(xh + off) = uh;
    *(uint4*)(xl + off) = ul;
}

// ===========================================================================
// Weight prep (coalesced transpose): w [K x N] fp32 -> hi/lo [NP][KP] bf16.
// ===========================================================================
__global__ __launch_bounds__(256)
void prep_w_kernel(const float* __restrict__ w,
                   __nv_bfloat16* __restrict__ dh,
                   __nv_bfloat16* __restrict__ dl,
                   int K, int N, int KP, int NP)
{
    __shared__ float t[32][33];
    int kb = blockIdx.x * 32;
    int nb = blockIdx.y * 32;
    int tx = threadIdx.x & 31;
    int ty = threadIdx.x >> 5;     // 0..7
#pragma unroll
    for (int i = ty; i < 32; i += 8) {
        int k = kb + i, n = nb + tx;
        t[i][tx] = (k < K && n < N) ? w[(size_t)k * N + n] : 0.f;
    }
    __syncthreads();
#pragma unroll
    for (int i = ty; i < 32; i += 8) {
        int n = nb + i, k = kb + tx;
        if (n < NP && k < KP) {
            __nv_bfloat16 h, l;
            split2(t[tx][i], h, l);
            size_t o = (size_t)n * KP + k;
            dh[o] = h; dl[o] = l;
        }
    }
}

// ===========================================================================
// CSR build
// ===========================================================================
__global__ void cnt_zero_kernel(int* __restrict__ cnt) {
    int i = blockIdx.x * 256 + threadIdx.x;
    if (i < NNP) cnt[i] = 0;
}
__global__ void hist_kernel(const int* __restrict__ ed, int* __restrict__ cnt, int E) {
    int e = blockIdx.x * 256 + threadIdx.x;
    if (e < E) atomicAdd(&cnt[ed[e]], 1);
}
__global__ void scan1_kernel(const int* __restrict__ cnt, int* __restrict__ part,
                             int* __restrict__ aux, int n)
{
    __shared__ int s[256];
    int tid = threadIdx.x;
    int g = blockIdx.x * 256 + tid;
    int v = (g < n) ? cnt[g] : 0;
    s[tid] = v;
    __syncthreads();
#pragma unroll
    for (int o = 1; o < 256; o <<= 1) {
        int t = (tid >= o) ? s[tid - o] : 0;
        __syncthreads();
        s[tid] += t;
        __syncthreads();
    }
    if (g < n) part[g] = s[tid] - v;
    if (tid == 255) aux[blockIdx.x] = s[tid];
}
__global__ void scan2_kernel(int* __restrict__ aux, int nb)
{
    __shared__ int s[256];
    int tid = threadIdx.x;
    int v = (tid < nb) ? aux[tid] : 0;
    s[tid] = v;
    __syncthreads();
#pragma unroll
    for (int o = 1; o < 256; o <<= 1) {
        int t = (tid >= o) ? s[tid - o] : 0;
        __syncthreads();
        s[tid] += t;
        __syncthreads();
    }
    if (tid < nb) aux[tid] = s[tid] - v;   // exclusive
}
__global__ void scan3_kernel(const int* __restrict__ part, const int* __restrict__ aux,
                             int* __restrict__ ptr, int* __restrict__ wp, int n, int E)
{
    int g = blockIdx.x * 256 + threadIdx.x;
    if (g < n) {
        int v = part[g] + aux[g >> 8];
        ptr[g] = v;
        wp[g] = v;
    }
    if (g == 0) ptr[n] = E;
}
__global__ void fill_kernel(const int* __restrict__ es, const int* __restrict__ ed,
                            const float* __restrict__ ew, int* __restrict__ wp,
                            int* __restrict__ csrc, float* __restrict__ cw, int E)
{
    int e = blockIdx.x * 256 + threadIdx.x;
    if (e >= E) return;
    int d = ed[e];
    int p = atomicAdd(&wp[d], 1);
    csrc[p] = es[e];
    cw[p] = ew[e];
}

// ===========================================================================
// HMMA GEMM: C[M x 512] = A[M x K] @ B^T[512 x K], bf16 3-term split.
// Output stored fp16 (consumed only by aggregation; halves z traffic).
// CTA 128x128, BK=32, 256 threads, warp tile 64x32 (2m x 4n warps)
// 2-stage cp.async pipeline (R3/R5-proven structure — mainloop untouched).
// ===========================================================================
#define STG 32768

__global__ __launch_bounds__(256)
void gemm_hmma_kernel(const __nv_bfloat16* __restrict__ Ah,
                      const __nv_bfloat16* __restrict__ Al, int lda,
                      const __nv_bfloat16* __restrict__ Bh,
                      const __nv_bfloat16* __restrict__ Bl, int ldb,
                      __half* __restrict__ C, int ldc, int nkc)
{
    extern __shared__ char smem[];
    const uint32_t sb = smem_to_u32(smem);
    const int tid  = threadIdx.x;
    const int lane = tid & 31;
    const int wid  = tid >> 5;
    const int m0 = blockIdx.y * 128;
    const int n0 = blockIdx.x * 128;
    const int wm = (wid >> 2) * 64;
    const int wn = (wid & 3) * 32;

    float acc[4][4][4];
#pragma unroll
    for (int i = 0; i < 4; i++)
#pragma unroll
        for (int j = 0; j < 4; j++)
#pragma unroll
            for (int q = 0; q < 4; q++) acc[i][j][q] = 0.f;

    auto load_stage = [&](int kc, int s) {
        int kk = kc * 32;
#pragma unroll
        for (int j = 0; j < 8; j++) {
            int id = tid + j * 256;
            int tile = id >> 9;               // 0..3
            int r = (id >> 2) & 127;
            int c = id & 3;
            uint32_t soff = sb + s * STG + tile * 8192 + r * 64
                          + ((c ^ ((r >> 1) & 3)) << 4);
            const __nv_bfloat16* g;
            if (tile == 0)      g = Ah + (size_t)(m0 + r) * lda + kk + c * 8;
            else if (tile == 1) g = Al + (size_t)(m0 + r) * lda + kk + c * 8;
            else if (tile == 2) g = Bh + (size_t)(n0 + r) * ldb + kk + c * 8;
            else                g = Bl + (size_t)(n0 + r) * ldb + kk + c * 8;
            cp16(soff, g);
        }
        asm volatile("cp.async.commit_group;");
    };

    load_stage(0, 0);

    for (int kc = 0; kc < nkc; kc++) {
        int s = kc & 1;
        if (kc + 1 < nkc) {
            load_stage(kc + 1, s ^ 1);
            asm volatile("cp.async.wait_group 1;");
        } else {
            asm volatile("cp.async.wait_group 0;");
        }
        __syncthreads();

        uint32_t tAh = sb + s * STG;
        uint32_t tAl = tAh + 8192;
        uint32_t tBh = tAh + 16384;
        uint32_t tBl = tAh + 24576;

#pragma unroll
        for (int kh = 0; kh < 2; kh++) {
            uint32_t ah[4][4], al[4][4], bh[2][4], bl[2][4];
            const int rlo = lane & 15;
            const int q   = 2 * kh + (lane >> 4);
#pragma unroll
            for (int i = 0; i < 4; i++) {
                int r = wm + i * 16 + rlo;
                uint32_t off = r * 64 + ((q ^ ((r >> 1) & 3)) << 4);
                ldsm4(ah[i][0], ah[i][1], ah[i][2], ah[i][3], tAh + off);
                ldsm4(al[i][0], al[i][1], al[i][2], al[i][3], tAl + off);
            }
#pragma unroll
            for (int j = 0; j < 2; j++) {
                int r = wn + j * 16 + rlo;
                uint32_t off = r * 64 + ((q ^ ((r >> 1) & 3)) << 4);
                ldsm4(bh[j][0], bh[j][1], bh[j][2], bh[j][3], tBh + off);
                ldsm4(bl[j][0], bl[j][1], bl[j][2], bl[j][3], tBl + off);
            }
#pragma unroll
            for (int i = 0; i < 4; i++) {
#pragma unroll
                for (int jj = 0; jj < 4; jj++) {
                    uint32_t bh0 = bh[jj >> 1][jj & 1];
                    uint32_t bh1 = bh[jj >> 1][(jj & 1) + 2];
                    uint32_t bl0 = bl[jj >> 1][jj & 1];
                    uint32_t bl1 = bl[jj >> 1][(jj & 1) + 2];
                    mma16816(acc[i][jj], ah[i], bh0, bh1);
                    mma16816(acc[i][jj], ah[i], bl0, bl1);
                    mma16816(acc[i][jj], al[i], bh0, bh1);
                }
            }
        }
        __syncthreads();
    }

    // epilogue: fp32 acc -> fp16 stores (half the write traffic)
#pragma unroll
    for (int i = 0; i < 4; i++) {
        int row = m0 + wm + i * 16 + (lane >> 2);
#pragma unroll
        for (int jj = 0; jj < 4; jj++) {
            int col = n0 + wn + jj * 8 + 2 * (lane & 3);
            __half2 v0 = __floats2half2_rn(acc[i][jj][0], acc[i][jj][1]);
            __half2 v1 = __floats2half2_rn(acc[i][jj][2], acc[i][jj][3]);
            *(__half2*)(C + (size_t)row * ldc + col) = v0;
            *(__half2*)(C + (size_t)(row + 8) * ldc + col) = v1;
        }
    }
}

// ===========================================================================
// Layer-1 CSR gather (fp16 z input): h1 = relu(agg(z1)+b1) -> bf16 hi/lo.
// 2-way edge unroll for MLP.
// ===========================================================================
__global__ __launch_bounds__(128)
void gather_kernel(const __half* __restrict__ src, const int* __restrict__ ptr,
                   const int* __restrict__ cs, const float* __restrict__ cw,
                   const float* __restrict__ bias,
                   __nv_bfloat16* __restrict__ oh, __nv_bfloat16* __restrict__ ol)
{
    int node = blockIdx.x;
    int tid = threadIdx.x;
    int beg = ptr[node], end = ptr[node + 1];
    const int c0 = tid, c1 = tid + 128, c2 = tid + 256, c3 = tid + 384;
    float a0 = 0.f, a1 = 0.f, a2 = 0.f, a3 = 0.f;
    float e0 = 0.f, e1 = 0.f, e2 = 0.f, e3 = 0.f;
    int i = beg;
    for (; i + 1 < end; i += 2) {
        int sA = cs[i],     sB = cs[i + 1];
        float wA = cw[i],   wB = cw[i + 1];
        const __half* pA = src + (size_t)sA * HSTR;
        const __half* pB = src + (size_t)sB * HSTR;
        a0 = fmaf(wA, __half2float(pA[c0]), a0);  e0 = fmaf(wB, __half2float(pB[c0]), e0);
        a1 = fmaf(wA, __half2float(pA[c1]), a1);  e1 = fmaf(wB, __half2float(pB[c1]), e1);
        a2 = fmaf(wA, __half2float(pA[c2]), a2);  e2 = fmaf(wB, __half2float(pB[c2]), e2);
        a3 = fmaf(wA, __half2float(pA[c3]), a3);  e3 = fmaf(wB, __half2float(pB[c3]), e3);
    }
    if (i < end) {
        int s = cs[i]; float w = cw[i];
        const __half* ps = src + (size_t)s * HSTR;
        a0 = fmaf(w, __half2float(ps[c0]), a0);
        a1 = fmaf(w, __half2float(ps[c1]), a1);
        a2 = fmaf(w, __half2float(ps[c2]), a2);
        a3 = fmaf(w, __half2float(ps[c3]), a3);
    }
    a0 += e0; a1 += e1; a2 += e2; a3 += e3;
    float v0 = fmaxf(a0 + bias[c0], 0.f);
    float v1 = fmaxf(a1 + bias[c1], 0.f);
    float v2 = fmaxf(a2 + bias[c2], 0.f);
    float v3 = fmaxf(a3 + ((c3 < HID) ? bias[c3] : 0.f), 0.f);
    size_t base = (size_t)node * HSTR;
    __nv_bfloat16 h, l;
    split2(v0, h, l); oh[base + c0] = h; ol[base + c0] = l;
    split2(v1, h, l); oh[base + c1] = h; ol[base + c1] = l;
    split2(v2, h, l); oh[base + c2] = h; ol[base + c2] = l;
    split2(v3, h, l); oh[base + c3] = h; ol[base + c3] = l;
}

// ===========================================================================
// Layer-2 gather (fp16 z input) fused with W3 projection.
// ===========================================================================
__global__ __launch_bounds__(128)
void gather_proj_kernel(const __half* __restrict__ src, const int* __restrict__ ptr,
                        const int* __restrict__ cs, const float* __restrict__ cw,
                        const float* __restrict__ bias,
                        const float* __restrict__ w3,
                        float* __restrict__ s1)
{
    __shared__ float red[6][128];
    int node = blockIdx.x;
    int tid = threadIdx.x;
    int beg = ptr[node], end = ptr[node + 1];
    const int c0 = tid, c1 = tid + 128, c2 = tid + 256, c3 = tid + 384;
    float a0 = 0.f, a1 = 0.f, a2 = 0.f, a3 = 0.f;
    float e0 = 0.f, e1 = 0.f, e2 = 0.f, e3 = 0.f;
    int i = beg;
    for (; i + 1 < end; i += 2) {
        int sA = cs[i],     sB = cs[i + 1];
        float wA = cw[i],   wB = cw[i + 1];
        const __half* pA = src + (size_t)sA * HSTR;
        const __half* pB = src + (size_t)sB * HSTR;
        a0 = fmaf(wA, __half2float(pA[c0]), a0);  e0 = fmaf(wB, __half2float(pB[c0]), e0);
        a1 = fmaf(wA, __half2float(pA[c1]), a1);  e1 = fmaf(wB, __half2float(pB[c1]), e1);
        a2 = fmaf(wA, __half2float(pA[c2]), a2);  e2 = fmaf(wB, __half2float(pB[c2]), e2);
        a3 = fmaf(wA, __half2float(pA[c3]), a3);  e3 = fmaf(wB, __half2float(pB[c3]), e3);
    }
    if (i < end) {
        int s = cs[i]; float w = cw[i];
        const __half* ps = src + (size_t)s * HSTR;
        a0 = fmaf(w, __half2float(ps[c0]), a0);
        a1 = fmaf(w, __half2float(ps[c1]), a1);
        a2 = fmaf(w, __half2float(ps[c2]), a2);
        a3 = fmaf(w, __half2float(ps[c3]), a3);
    }
    a0 += e0; a1 += e1; a2 += e2; a3 += e3;
    float v0 = fmaxf(a0 + bias[c0], 0.f);
    float v1 = fmaxf(a1 + bias[c1], 0.f);
    float v2 = fmaxf(a2 + bias[c2], 0.f);
    float v3 = (c3 < HID) ? fmaxf(a3 + bias[c3], 0.f) : 0.f;

    float p[6] = {0.f, 0.f, 0.f, 0.f, 0.f, 0.f};
    const float* r0 = w3 + (size_t)c0 * 6;
    const float* r1 = w3 + (size_t)c1 * 6;
    const float* r2 = w3 + (size_t)c2 * 6;
#pragma unroll
    for (int j = 0; j < 6; j++) {
        float t = v0 * __ldg(&r0[j]) + v1 * __ldg(&r1[j]) + v2 * __ldg(&r2[j]);
        if (c3 < HID) t += v3 * __ldg(&w3[(size_t)c3 * 6 + j]);
        p[j] = t;
    }
#pragma unroll
    for (int j = 0; j < 6; j++) red[j][tid] = p[j];
    __syncthreads();
#pragma unroll
    for (int s = 64; s >= 1; s >>= 1) {
        if (tid < s) {
#pragma unroll
            for (int j = 0; j < 6; j++) red[j][tid] += red[j][tid + s];
        }
        __syncthreads();
    }
    if (tid < 6) s1[(size_t)node * 8 + tid] = red[tid][0];
}

// ===========================================================================
// Final fused: aggregate (CSR) + b3 + log_softmax, warp per node
// ===========================================================================
__global__ void final_kernel(const float* __restrict__ s1, const int* __restrict__ ptr,
                             const int* __restrict__ cs, const float* __restrict__ cw,
                             const float* __restrict__ b3, float* __restrict__ out, int M)
{
    int node = (blockIdx.x * blockDim.x + threadIdx.x) >> 5;
    int lane = threadIdx.x & 31;
    if (node >= M) return;
    int beg = ptr[node], end = ptr[node + 1];
    float a[6] = {0.f, 0.f, 0.f, 0.f, 0.f, 0.f};
    for (int i = beg + lane; i < end; i += 32) {
        int s = cs[i];
        float w = cw[i];
        const float* ps = s1 + (size_t)s * 8;
#pragma unroll
        for (int j = 0; j < 6; j++) a[j] = fmaf(w, ps[j], a[j]);
    }
#pragma unroll
    for (int j = 0; j < 6; j++)
#pragma unroll
        for (int off = 16; off > 0; off >>= 1)
            a[j] += __shfl_xor_sync(0xffffffffu, a[j], off);
    if (lane == 0) {
        float v[6];
#pragma unroll
        for (int j = 0; j < 6; j++) v[j] = a[j] + b3[j];
        float m = v[0];
#pragma unroll
        for (int j = 1; j < 6; j++) m = fmaxf(m, v[j]);
        float s = 0.f;
#pragma unroll
        for (int j = 0; j < 6; j++) s += __expf(v[j] - m);
        float l = logf(s) + m;
        float* po = out + (size_t)node * 6;
#pragma unroll
        for (int j = 0; j < 6; j++) po[j] = v[j] - l;
    }
}

// ===========================================================================
// Launch
// ===========================================================================
extern "C" void kernel_launch(void* const* d_in, const int* in_sizes, int n_in,
                              void* d_out, int out_size)
{
    const float* x   = (const float*)d_in[0];
    const float* w1  = (const float*)d_in[1];
    const float* b1  = (const float*)d_in[2];
    const float* w2  = (const float*)d_in[3];
    const float* b2  = (const float*)d_in[4];
    const float* w3  = (const float*)d_in[5];
    const float* b3  = (const float*)d_in[6];
    const float* ew  = (const float*)d_in[7];
    const int*   es  = (const int*)d_in[8];
    const int*   ed  = (const int*)d_in[9];
    float* out = (float*)d_out;

    const int E = in_sizes[7];

    __nv_bfloat16 *xhi, *xlo, *w1hi, *w1lo, *w2hi, *w2lo, *hhi, *hlo;
    __half *pz;
    float *ps1, *cwv;
    int *cnt, *part, *aux, *ptr, *wp, *csrc;
    cudaGetSymbolAddress((void**)&xhi,  g_xhi);
    cudaGetSymbolAddress((void**)&xlo,  g_xlo);
    cudaGetSymbolAddress((void**)&w1hi, g_w1hi);
    cudaGetSymbolAddress((void**)&w1lo, g_w1lo);
    cudaGetSymbolAddress((void**)&w2hi, g_w2hi);
    cudaGetSymbolAddress((void**)&w2lo, g_w2lo);
    cudaGetSymbolAddress((void**)&hhi,  g_hhi);
    cudaGetSymbolAddress((void**)&hlo,  g_hlo);
    cudaGetSymbolAddress((void**)&pz,   g_z);
    cudaGetSymbolAddress((void**)&ps1,  g_s1);
    cudaGetSymbolAddress((void**)&cnt,  g_cnt);
    cudaGetSymbolAddress((void**)&part, g_part);
    cudaGetSymbolAddress((void**)&aux,  g_aux);
    cudaGetSymbolAddress((void**)&ptr,  g_ptr);
    cudaGetSymbolAddress((void**)&wp,   g_wp);
    cudaGetSymbolAddress((void**)&csrc, g_csrc);
    cudaGetSymbolAddress((void**)&cwv,  g_cw);

    cudaFuncSetAttribute(gemm_hmma_kernel,
                         cudaFuncAttributeMaxDynamicSharedMemorySize, 2 * STG);

    dim3 ggrid(HSTR / 128, NNP / 128);   // (4, 391), N fastest for A L2 reuse

    // ---- input prep (gemm1 stays launch #4 for ncu) ----
    {
        int total = NN * XCHUNKS;
        split_x_kernel<<<(total + 255) / 256, 256>>>(x, xhi, xlo);           // #1
    }
    {
        dim3 g1((INDP + 31) / 32, (HSTR + 31) / 32);
        prep_w_kernel<<<g1, 256>>>(w1, w1hi, w1lo, IND, HID, INDP, HSTR);    // #2
        dim3 g2((HSTR + 31) / 32, (HSTR + 31) / 32);
        prep_w_kernel<<<g2, 256>>>(w2, w2hi, w2lo, HID, HID, HSTR, HSTR);    // #3
    }

    // ---- Layer 1 GEMM ----                                                // #4
    gemm_hmma_kernel<<<ggrid, 256, 2 * STG>>>(xhi, xlo, INDP, w1hi, w1lo, INDP,
                                              pz, HSTR, INDP / 32);

    // ---- CSR build ----
    cnt_zero_kernel<<<(NNP + 255) / 256, 256>>>(cnt);
    hist_kernel<<<(E + 255) / 256, 256>>>(ed, cnt, E);
    {
        int nb = (NN + 255) / 256;   // 196
        scan1_kernel<<<nb, 256>>>(cnt, part, aux, NN);
        scan2_kernel<<<1, 256>>>(aux, nb);
        scan3_kernel<<<nb, 256>>>(part, aux, ptr, wp, NN, E);
    }
    fill_kernel<<<(E + 255) / 256, 256>>>(es, ed, ew, wp, csrc, cwv, E);

    // ---- Layer 1 aggregate ----
    gather_kernel<<<NN, 128>>>(pz, ptr, csrc, cwv, b1, hhi, hlo);

    // ---- Layer 2 GEMM + fused aggregate/projection ----
    gemm_hmma_kernel<<<ggrid, 256, 2 * STG>>>(hhi, hlo, HSTR, w2hi, w2lo, HSTR,
                                              pz, HSTR, HSTR / 32);
    gather_proj_kernel<<<NN, 128>>>(pz, ptr, csrc, cwv, b2, w3, ps1);

    // ---- Layer 3 aggregate + log_softmax ----
    final_kernel<<<(NN + 7) / 8, 256>>>(ps1, ptr, csrc, cwv, b3, out, NN);

    (void)n_in; (void)out_size;
}

// round 9
// speedup vs baseline: 2.9433x; 1.9315x over previous
#include <cuda_runtime.h>
#include <cuda_fp16.h>
#include <math.h>
#include <stdint.h>

// ===========================================================================
// Problem constants (fixed shapes)
// ===========================================================================
#define NN     50000          // nodes
#define NNP    50048          // padded to 128
#define IND    3703           // input dim
#define INDP   3712           // padded to 64
#define HID    500
#define HSTR   512            // padded hidden
#define EMAX   1000000

// ===========================================================================
// Device scratch (static globals; no dynamic allocation)
// ===========================================================================
__device__ __half g_xh[(size_t)NNP * INDP];
__device__ __half g_w1[HSTR * INDP];
__device__ __half g_w2b[HSTR * HSTR];
__device__ __half g_h[(size_t)NNP * HSTR];
__device__ __half g_z[(size_t)NNP * HSTR];   // GEMM output (fp16)
__device__ float g_s1[(size_t)NNP * 8];      // layer-3 per-node logits (pre-agg)

__device__ int   g_cnt[NNP];
__device__ int   g_part[NNP];
__device__ int   g_aux[256];
__device__ int   g_ptr[NN + 1];
__device__ int   g_wp[NNP];
__device__ int   g_csrc[EMAX];
__device__ float g_cw[EMAX];

// ===========================================================================
// Helpers
// ===========================================================================
__device__ __forceinline__ uint32_t smem_to_u32(const void* p) {
    uint32_t a;
    asm("{ .reg .u64 t; cvta.to.shared.u64 t, %1; cvt.u32.u64 %0, t; }"
        : "=r"(a) : "l"(p));
    return a;
}
__device__ __forceinline__ void ldsm4(uint32_t& r0, uint32_t& r1,
                                      uint32_t& r2, uint32_t& r3, uint32_t addr) {
    asm volatile("ldmatrix.sync.aligned.m8n8.x4.shared.b16 {%0,%1,%2,%3}, [%4];"
        : "=r"(r0), "=r"(r1), "=r"(r2), "=r"(r3) : "r"(addr));
}
__device__ __forceinline__ void mma16816(float* c, const uint32_t* a,
                                         uint32_t b0, uint32_t b1) {
    asm volatile("mma.sync.aligned.m16n8k16.row.col.f32.f16.f16.f32 "
        "{%0,%1,%2,%3}, {%4,%5,%6,%7}, {%8,%9}, {%0,%1,%2,%3};"
        : "+f"(c[0]), "+f"(c[1]), "+f"(c[2]), "+f"(c[3])
        : "r"(a[0]), "r"(a[1]), "r"(a[2]), "r"(a[3]), "r"(b0), "r"(b1));
}
__device__ __forceinline__ void cp16(uint32_t soff, const void* g) {
    asm volatile("cp.async.cg.shared.global [%0], [%1], 16;" :: "r"(soff), "l"(g));
}
__device__ __forceinline__ uint32_t pkh(__half a, __half b) {
    return (uint32_t)__half_as_ushort(a) | ((uint32_t)__half_as_ushort(b) << 16);
}

// ===========================================================================
// X -> fp16 (rows 0..NN-1; pad rows stay zero)
// ===========================================================================
#define XCHUNKS (INDP / 8)   // 464
__global__ __launch_bounds__(256)
void split_x_kernel(const float* __restrict__ x, __half* __restrict__ xh)
{
    int idx = blockIdx.x * 256 + threadIdx.x;
    int total = NN * XCHUNKS;
    if (idx >= total) return;
    int row = idx / XCHUNKS;
    int cb  = (idx - row * XCHUNKS) * 8;
    const float* px = x + (size_t)row * IND;
    __half hh[8];
#pragma unroll
    for (int j = 0; j < 8; j++) {
        int c = cb + j;
        hh[j] = __float2half_rn((c < IND) ? px[c] : 0.f);
    }
    size_t off = (size_t)row * INDP + cb;
    uint4 uh;
    uh.x = pkh(hh[0], hh[1]); uh.y = pkh(hh[2], hh[3]);
    uh.z = pkh(hh[4], hh[5]); uh.w = pkh(hh[6], hh[7]);
    *(uint4*)(xh + off) = uh;
}

// ===========================================================================
// Weight prep (coalesced transpose): w [K x N] fp32 -> fp16 [NP][KP]
// ===========================================================================
__global__ __launch_bounds__(256)
void prep_w_kernel(const float* __restrict__ w, __half* __restrict__ dh,
                   int K, int N, int KP, int NP)
{
    __shared__ float t[32][33];
    int kb = blockIdx.x * 32;
    int nb = blockIdx.y * 32;
    int tx = threadIdx.x & 31;
    int ty = threadIdx.x >> 5;     // 0..7
#pragma unroll
    for (int i = ty; i < 32; i += 8) {
        int k = kb + i, n = nb + tx;
        t[i][tx] = (k < K && n < N) ? w[(size_t)k * N + n] : 0.f;
    }
    __syncthreads();
#pragma unroll
    for (int i = ty; i < 32; i += 8) {
        int n = nb + i, k = kb + tx;
        if (n < NP && k < KP)
            dh[(size_t)n * KP + k] = __float2half_rn(t[tx][i]);
    }
}

// ===========================================================================
// CSR build
// ===========================================================================
__global__ void cnt_zero_kernel(int* __restrict__ cnt) {
    int i = blockIdx.x * 256 + threadIdx.x;
    if (i < NNP) cnt[i] = 0;
}
__global__ void hist_kernel(const int* __restrict__ ed, int* __restrict__ cnt, int E) {
    int e = blockIdx.x * 256 + threadIdx.x;
    if (e < E) atomicAdd(&cnt[ed[e]], 1);
}
__global__ void scan1_kernel(const int* __restrict__ cnt, int* __restrict__ part,
                             int* __restrict__ aux, int n)
{
    __shared__ int s[256];
    int tid = threadIdx.x;
    int g = blockIdx.x * 256 + tid;
    int v = (g < n) ? cnt[g] : 0;
    s[tid] = v;
    __syncthreads();
#pragma unroll
    for (int o = 1; o < 256; o <<= 1) {
        int t = (tid >= o) ? s[tid - o] : 0;
        __syncthreads();
        s[tid] += t;
        __syncthreads();
    }
    if (g < n) part[g] = s[tid] - v;
    if (tid == 255) aux[blockIdx.x] = s[tid];
}
__global__ void scan2_kernel(int* __restrict__ aux, int nb)
{
    __shared__ int s[256];
    int tid = threadIdx.x;
    int v = (tid < nb) ? aux[tid] : 0;
    s[tid] = v;
    __syncthreads();
#pragma unroll
    for (int o = 1; o < 256; o <<= 1) {
        int t = (tid >= o) ? s[tid - o] : 0;
        __syncthreads();
        s[tid] += t;
        __syncthreads();
    }
    if (tid < nb) aux[tid] = s[tid] - v;   // exclusive
}
__global__ void scan3_kernel(const int* __restrict__ part, const int* __restrict__ aux,
                             int* __restrict__ ptr, int* __restrict__ wp, int n, int E)
{
    int g = blockIdx.x * 256 + threadIdx.x;
    if (g < n) {
        int v = part[g] + aux[g >> 8];
        ptr[g] = v;
        wp[g] = v;
    }
    if (g == 0) ptr[n] = E;
}
__global__ void fill_kernel(const int* __restrict__ es, const int* __restrict__ ed,
                            const float* __restrict__ ew, int* __restrict__ wp,
                            int* __restrict__ csrc, float* __restrict__ cw, int E)
{
    int e = blockIdx.x * 256 + threadIdx.x;
    if (e >= E) return;
    int d = ed[e];
    int p = atomicAdd(&wp[d], 1);
    csrc[p] = es[e];
    cw[p] = ew[e];
}

// ===========================================================================
// HMMA GEMM: C[M x 512] = A[M x K] @ B^T[512 x K], fp16 operands, fp32 accum.
// Same proven 2-stage cp.async pipeline as R3/R5; tiles {A, B}.
// CTA 128x128, BK=32, 256 threads, warp tile 64x32 (2m x 4n warps).
// Stage = A(8KB) + B(8KB) = 16KB. Swizzle: chunk c of row r at c^((r>>1)&3).
// ===========================================================================
#define STG 16384

__global__ __launch_bounds__(256)
void gemm_hmma_kernel(const __half* __restrict__ Ah, int lda,
                      const __half* __restrict__ Bh, int ldb,
                      __half* __restrict__ C, int ldc, int nkc)
{
    extern __shared__ char smem[];
    const uint32_t sb = smem_to_u32(smem);
    const int tid  = threadIdx.x;
    const int lane = tid & 31;
    const int wid  = tid >> 5;
    const int m0 = blockIdx.y * 128;
    const int n0 = blockIdx.x * 128;
    const int wm = (wid >> 2) * 64;
    const int wn = (wid & 3) * 32;

    float acc[4][4][4];
#pragma unroll
    for (int i = 0; i < 4; i++)
#pragma unroll
        for (int j = 0; j < 4; j++)
#pragma unroll
            for (int q = 0; q < 4; q++) acc[i][j][q] = 0.f;

    auto load_stage = [&](int kc, int s) {
        int kk = kc * 32;
#pragma unroll
        for (int j = 0; j < 4; j++) {
            int id = tid + j * 256;
            int tile = id >> 9;               // 0..1
            int r = (id >> 2) & 127;
            int c = id & 3;
            uint32_t soff = sb + s * STG + tile * 8192 + r * 64
                          + ((c ^ ((r >> 1) & 3)) << 4);
            const __half* g;
            if (tile == 0) g = Ah + (size_t)(m0 + r) * lda + kk + c * 8;
            else           g = Bh + (size_t)(n0 + r) * ldb + kk + c * 8;
            cp16(soff, g);
        }
        asm volatile("cp.async.commit_group;");
    };

    load_stage(0, 0);

    for (int kc = 0; kc < nkc; kc++) {
        int s = kc & 1;
        if (kc + 1 < nkc) {
            load_stage(kc + 1, s ^ 1);
            asm volatile("cp.async.wait_group 1;");
        } else {
            asm volatile("cp.async.wait_group 0;");
        }
        __syncthreads();

        uint32_t tAh = sb + s * STG;
        uint32_t tBh = tAh + 8192;

#pragma unroll
        for (int kh = 0; kh < 2; kh++) {
            uint32_t ah[4][4], bh[2][4];
            const int rlo = lane & 15;
            const int q   = 2 * kh + (lane >> 4);
#pragma unroll
            for (int i = 0; i < 4; i++) {
                int r = wm + i * 16 + rlo;
                uint32_t off = r * 64 + ((q ^ ((r >> 1) & 3)) << 4);
                ldsm4(ah[i][0], ah[i][1], ah[i][2], ah[i][3], tAh + off);
            }
#pragma unroll
            for (int j = 0; j < 2; j++) {
                int r = wn + j * 16 + rlo;
                uint32_t off = r * 64 + ((q ^ ((r >> 1) & 3)) << 4);
                ldsm4(bh[j][0], bh[j][1], bh[j][2], bh[j][3], tBh + off);
            }
#pragma unroll
            for (int i = 0; i < 4; i++) {
#pragma unroll
                for (int jj = 0; jj < 4; jj++) {
                    uint32_t b0 = bh[jj >> 1][jj & 1];
                    uint32_t b1 = bh[jj >> 1][(jj & 1) + 2];
                    mma16816(acc[i][jj], ah[i], b0, b1);
                }
            }
        }
        __syncthreads();
    }

    // epilogue: fp32 acc -> fp16 stores
#pragma unroll
    for (int i = 0; i < 4; i++) {
        int row = m0 + wm + i * 16 + (lane >> 2);
#pragma unroll
        for (int jj = 0; jj < 4; jj++) {
            int col = n0 + wn + jj * 8 + 2 * (lane & 3);
            __half2 v0 = __floats2half2_rn(acc[i][jj][0], acc[i][jj][1]);
            __half2 v1 = __floats2half2_rn(acc[i][jj][2], acc[i][jj][3]);
            *(__half2*)(C + (size_t)row * ldc + col) = v0;
            *(__half2*)(C + (size_t)(row + 8) * ldc + col) = v1;
        }
    }
}

// ===========================================================================
// Layer-1 CSR gather (fp16 z input): h1 = relu(agg(z1)+b1) -> fp16.
// 2-way edge unroll for MLP.
// ===========================================================================
__global__ __launch_bounds__(128)
void gather_kernel(const __half* __restrict__ src, const int* __restrict__ ptr,
                   const int* __restrict__ cs, const float* __restrict__ cw,
                   const float* __restrict__ bias,
                   __half* __restrict__ oh)
{
    int node = blockIdx.x;
    int tid = threadIdx.x;
    int beg = ptr[node], end = ptr[node + 1];
    const int c0 = tid, c1 = tid + 128, c2 = tid + 256, c3 = tid + 384;
    float a0 = 0.f, a1 = 0.f, a2 = 0.f, a3 = 0.f;
    float e0 = 0.f, e1 = 0.f, e2 = 0.f, e3 = 0.f;
    int i = beg;
    for (; i + 1 < end; i += 2) {
        int sA = cs[i],     sB = cs[i + 1];
        float wA = cw[i],   wB = cw[i + 1];
        const __half* pA = src + (size_t)sA * HSTR;
        const __half* pB = src + (size_t)sB * HSTR;
        a0 = fmaf(wA, __half2float(pA[c0]), a0);  e0 = fmaf(wB, __half2float(pB[c0]), e0);
        a1 = fmaf(wA, __half2float(pA[c1]), a1);  e1 = fmaf(wB, __half2float(pB[c1]), e1);
        a2 = fmaf(wA, __half2float(pA[c2]), a2);  e2 = fmaf(wB, __half2float(pB[c2]), e2);
        a3 = fmaf(wA, __half2float(pA[c3]), a3);  e3 = fmaf(wB, __half2float(pB[c3]), e3);
    }
    if (i < end) {
        int s = cs[i]; float w = cw[i];
        const __half* ps = src + (size_t)s * HSTR;
        a0 = fmaf(w, __half2float(ps[c0]), a0);
        a1 = fmaf(w, __half2float(ps[c1]), a1);
        a2 = fmaf(w, __half2float(ps[c2]), a2);
        a3 = fmaf(w, __half2float(ps[c3]), a3);
    }
    a0 += e0; a1 += e1; a2 += e2; a3 += e3;
    float v0 = fmaxf(a0 + bias[c0], 0.f);
    float v1 = fmaxf(a1 + bias[c1], 0.f);
    float v2 = fmaxf(a2 + bias[c2], 0.f);
    float v3 = fmaxf(a3 + ((c3 < HID) ? bias[c3] : 0.f), 0.f);
    size_t base = (size_t)node * HSTR;
    oh[base + c0] = __float2half_rn(v0);
    oh[base + c1] = __float2half_rn(v1);
    oh[base + c2] = __float2half_rn(v2);
    oh[base + c3] = __float2half_rn(v3);
}

// ===========================================================================
// Layer-2 gather (fp16 z input) fused with W3 projection.
// ===========================================================================
__global__ __launch_bounds__(128)
void gather_proj_kernel(const __half* __restrict__ src, const int* __restrict__ ptr,
                        const int* __restrict__ cs, const float* __restrict__ cw,
                        const float* __restrict__ bias,
                        const float* __restrict__ w3,
                        float* __restrict__ s1)
{
    __shared__ float red[6][128];
    int node = blockIdx.x;
    int tid = threadIdx.x;
    int beg = ptr[node], end = ptr[node + 1];
    const int c0 = tid, c1 = tid + 128, c2 = tid + 256, c3 = tid + 384;
    float a0 = 0.f, a1 = 0.f, a2 = 0.f, a3 = 0.f;
    float e0 = 0.f, e1 = 0.f, e2 = 0.f, e3 = 0.f;
    int i = beg;
    for (; i + 1 < end; i += 2) {
        int sA = cs[i],     sB = cs[i + 1];
        float wA = cw[i],   wB = cw[i + 1];
        const __half* pA = src + (size_t)sA * HSTR;
        const __half* pB = src + (size_t)sB * HSTR;
        a0 = fmaf(wA, __half2float(pA[c0]), a0);  e0 = fmaf(wB, __half2float(pB[c0]), e0);
        a1 = fmaf(wA, __half2float(pA[c1]), a1);  e1 = fmaf(wB, __half2float(pB[c1]), e1);
        a2 = fmaf(wA, __half2float(pA[c2]), a2);  e2 = fmaf(wB, __half2float(pB[c2]), e2);
        a3 = fmaf(wA, __half2float(pA[c3]), a3);  e3 = fmaf(wB, __half2float(pB[c3]), e3);
    }
    if (i < end) {
        int s = cs[i]; float w = cw[i];
        const __half* ps = src + (size_t)s * HSTR;
        a0 = fmaf(w, __half2float(ps[c0]), a0);
        a1 = fmaf(w, __half2float(ps[c1]), a1);
        a2 = fmaf(w, __half2float(ps[c2]), a2);
        a3 = fmaf(w, __half2float(ps[c3]), a3);
    }
    a0 += e0; a1 += e1; a2 += e2; a3 += e3;
    float v0 = fmaxf(a0 + bias[c0], 0.f);
    float v1 = fmaxf(a1 + bias[c1], 0.f);
    float v2 = fmaxf(a2 + bias[c2], 0.f);
    float v3 = (c3 < HID) ? fmaxf(a3 + bias[c3], 0.f) : 0.f;

    float p[6] = {0.f, 0.f, 0.f, 0.f, 0.f, 0.f};
    const float* r0 = w3 + (size_t)c0 * 6;
    const float* r1 = w3 + (size_t)c1 * 6;
    const float* r2 = w3 + (size_t)c2 * 6;
#pragma unroll
    for (int j = 0; j < 6; j++) {
        float t = v0 * __ldg(&r0[j]) + v1 * __ldg(&r1[j]) + v2 * __ldg(&r2[j]);
        if (c3 < HID) t += v3 * __ldg(&w3[(size_t)c3 * 6 + j]);
        p[j] = t;
    }
#pragma unroll
    for (int j = 0; j < 6; j++) red[j][tid] = p[j];
    __syncthreads();
#pragma unroll
    for (int s = 64; s >= 1; s >>= 1) {
        if (tid < s) {
#pragma unroll
            for (int j = 0; j < 6; j++) red[j][tid] += red[j][tid + s];
        }
        __syncthreads();
    }
    if (tid < 6) s1[(size_t)node * 8 + tid] = red[tid][0];
}

// ===========================================================================
// Final fused: aggregate (CSR) + b3 + log_softmax, warp per node
// ===========================================================================
__global__ void final_kernel(const float* __restrict__ s1, const int* __restrict__ ptr,
                             const int* __restrict__ cs, const float* __restrict__ cw,
                             const float* __restrict__ b3, float* __restrict__ out, int M)
{
    int node = (blockIdx.x * blockDim.x + threadIdx.x) >> 5;
    int lane = threadIdx.x & 31;
    if (node >= M) return;
    int beg = ptr[node], end = ptr[node + 1];
    float a[6] = {0.f, 0.f, 0.f, 0.f, 0.f, 0.f};
    for (int i = beg + lane; i < end; i += 32) {
        int s = cs[i];
        float w = cw[i];
        const float* ps = s1 + (size_t)s * 8;
#pragma unroll
        for (int j = 0; j < 6; j++) a[j] = fmaf(w, ps[j], a[j]);
    }
#pragma unroll
    for (int j = 0; j < 6; j++)
#pragma unroll
        for (int off = 16; off > 0; off >>= 1)
            a[j] += __shfl_xor_sync(0xffffffffu, a[j], off);
    if (lane == 0) {
        float v[6];
#pragma unroll
        for (int j = 0; j < 6; j++) v[j] = a[j] + b3[j];
        float m = v[0];
#pragma unroll
        for (int j = 1; j < 6; j++) m = fmaxf(m, v[j]);
        float s = 0.f;
#pragma unroll
        for (int j = 0; j < 6; j++) s += __expf(v[j] - m);
        float l = logf(s) + m;
        float* po = out + (size_t)node * 6;
#pragma unroll
        for (int j = 0; j < 6; j++) po[j] = v[j] - l;
    }
}

// ===========================================================================
// Launch
// ===========================================================================
extern "C" void kernel_launch(void* const* d_in, const int* in_sizes, int n_in,
                              void* d_out, int out_size)
{
    const float* x   = (const float*)d_in[0];
    const float* w1  = (const float*)d_in[1];
    const float* b1  = (const float*)d_in[2];
    const float* w2  = (const float*)d_in[3];
    const float* b2  = (const float*)d_in[4];
    const float* w3  = (const float*)d_in[5];
    const float* b3  = (const float*)d_in[6];
    const float* ew  = (const float*)d_in[7];
    const int*   es  = (const int*)d_in[8];
    const int*   ed  = (const int*)d_in[9];
    float* out = (float*)d_out;

    const int E = in_sizes[7];

    __half *xh, *w1b, *w2b, *hb, *pz;
    float *ps1, *cwv;
    int *cnt, *part, *aux, *ptr, *wp, *csrc;
    cudaGetSymbolAddress((void**)&xh,   g_xh);
    cudaGetSymbolAddress((void**)&w1b,  g_w1);
    cudaGetSymbolAddress((void**)&w2b,  g_w2b);
    cudaGetSymbolAddress((void**)&hb,   g_h);
    cudaGetSymbolAddress((void**)&pz,   g_z);
    cudaGetSymbolAddress((void**)&ps1,  g_s1);
    cudaGetSymbolAddress((void**)&cnt,  g_cnt);
    cudaGetSymbolAddress((void**)&part, g_part);
    cudaGetSymbolAddress((void**)&aux,  g_aux);
    cudaGetSymbolAddress((void**)&ptr,  g_ptr);
    cudaGetSymbolAddress((void**)&wp,   g_wp);
    cudaGetSymbolAddress((void**)&csrc, g_csrc);
    cudaGetSymbolAddress((void**)&cwv,  g_cw);

    cudaFuncSetAttribute(gemm_hmma_kernel,
                         cudaFuncAttributeMaxDynamicSharedMemorySize, 2 * STG);

    dim3 ggrid(HSTR / 128, NNP / 128);   // (4, 391), N fastest for A L2 reuse

    // ---- input prep (gemm1 stays launch #4 for ncu) ----
    {
        int total = NN * XCHUNKS;
        split_x_kernel<<<(total + 255) / 256, 256>>>(x, xh);                 // #1
    }
    {
        dim3 g1((INDP + 31) / 32, (HSTR + 31) / 32);
        prep_w_kernel<<<g1, 256>>>(w1, w1b, IND, HID, INDP, HSTR);           // #2
        dim3 g2((HSTR + 31) / 32, (HSTR + 31) / 32);
        prep_w_kernel<<<g2, 256>>>(w2, w2b, HID, HID, HSTR, HSTR);           // #3
    }

    // ---- Layer 1 GEMM ----                                                // #4
    gemm_hmma_kernel<<<ggrid, 256, 2 * STG>>>(xh, INDP, w1b, INDP,
                                              pz, HSTR, INDP / 32);

    // ---- CSR build ----
    cnt_zero_kernel<<<(NNP + 255) / 256, 256>>>(cnt);
    hist_kernel<<<(E + 255) / 256, 256>>>(ed, cnt, E);
    {
        int nb = (NN + 255) / 256;   // 196
        scan1_kernel<<<nb, 256>>>(cnt, part, aux, NN);
        scan2_kernel<<<1, 256>>>(aux, nb);
        scan3_kernel<<<nb, 256>>>(part, aux, ptr, wp, NN, E);
    }
    fill_kernel<<<(E + 255) / 256, 256>>>(es, ed, ew, wp, csrc, cwv, E);

    // ---- Layer 1 aggregate ----
    gather_kernel<<<NN, 128>>>(pz, ptr, csrc, cwv, b1, hb);

    // ---- Layer 2 GEMM + fused aggregate/projection ----
    gemm_hmma_kernel<<<ggrid, 256, 2 * STG>>>(hb, HSTR, w2b, HSTR,
                                              pz, HSTR, HSTR / 32);
    gather_proj_kernel<<<NN, 128>>>(pz, ptr, csrc, cwv, b2, w3, ps1);

    // ---- Layer 3 aggregate + log_softmax ----
    final_kernel<<<(NN + 7) / 8, 256>>>(ps1, ptr, csrc, cwv, b3, out, NN);

    (void)n_in; (void)out_size;
}